// round 10
// baseline (speedup 1.0000x reference)
#include <cuda_runtime.h>
#include <math.h>

// ---------------------------------------------------------------------------
// CMAF fused block, round 10 = round 9 + attention fused into outproj:
//   k_attn eliminated; o computed thread-locally during outproj A-staging,
//   written tf32 into a smem-resident A buffer (128x136, conflict-free frags).
//   W-only 3-stage cp.async pipeline; 2 CTAs/SM preserved.
// ---------------------------------------------------------------------------

#define MAXB 65536
#define GPAD 24
#define GSMEM (3 * 2 * 128 * GPAD * 4)   // 73728 bytes (generic GEMM path)

#define AFPAD 136
#define OWS_IDX(s, r, c) (128 * AFPAD + ((s) * 128 + (r)) * GPAD + (c))
#define OSMEM ((128 * AFPAD + 3 * 128 * GPAD) * 4)   // 106496 bytes

__device__ __align__(16) float g_P [MAXB * 3 * 128];
__device__ __align__(16) float g_q [MAXB * 3 * 128];
__device__ __align__(16) float g_k [MAXB * 6 * 128];
__device__ __align__(16) float g_v [MAXB * 6 * 128];
__device__ __align__(16) float g_x1[MAXB * 3 * 128];
__device__ __align__(16) float g_h [MAXB * 3 * 256];
__device__ __align__(16) float g_x2[MAXB * 3 * 128];

// tf32-preconverted weights
#define WOFF_SPATIAL 0
#define WOFF_GF      163840
#define WOFF_INW     196608
#define WOFF_OUTW    344064
#define WOFF_FFN1    393216
#define WOFF_FFN2    491520
__device__ __align__(16) float g_wtf[589824];

// QKV jobs per source stream s: {w_off (within in_w), b_off, buf_id, out_off}
__constant__ int qkv_jobs[3][5][4] = {
    { {     0,    0, 0,   0}, { 65536,  512, 1, 256}, { 81920,  640, 2, 256},
      {114688,  896, 1, 512}, {131072, 1024, 2, 512} },
    { { 49152,  384, 0, 128}, { 16384,  128, 1,   0}, { 32768,  256, 2,   0},
      {114688,  896, 1, 640}, {131072, 1024, 2, 640} },
    { { 98304,  768, 0, 256}, { 16384,  128, 1, 128}, { 32768,  256, 2, 128},
      { 65536,  512, 1, 384}, { 81920,  640, 2, 384} },
};

__device__ __forceinline__ unsigned f2tf(float f) {
    unsigned u;
    asm("cvt.rna.tf32.f32 %0, %1;" : "=r"(u) : "f"(f));
    return u;
}
__device__ __forceinline__ float tfr(float f) {
    return __uint_as_float(f2tf(f));
}

__device__ __forceinline__ void mma8(float c[4], const unsigned a[4], const unsigned b[2]) {
    asm volatile(
        "mma.sync.aligned.m16n8k8.row.col.f32.tf32.tf32.f32 "
        "{%0,%1,%2,%3}, {%4,%5,%6,%7}, {%8,%9}, {%0,%1,%2,%3};\n"
        : "+f"(c[0]), "+f"(c[1]), "+f"(c[2]), "+f"(c[3])
        : "r"(a[0]), "r"(a[1]), "r"(a[2]), "r"(a[3]), "r"(b[0]), "r"(b[1]));
}

__device__ __forceinline__ void cp16(unsigned smem_dst, const void* gsrc) {
    asm volatile("cp.async.cg.shared.global [%0], [%1], 16;\n"
                 :: "r"(smem_dst), "l"(gsrc));
}
__device__ __forceinline__ void cp_commit() {
    asm volatile("cp.async.commit_group;\n");
}
template <int N>
__device__ __forceinline__ void cp_wait() {
    asm volatile("cp.async.wait_group %0;\n" :: "n"(N));
}

#define AS_IDX(s, r, c) (((s) * 128 + (r)) * GPAD + (c))
#define WS_IDX(s, r, c) (3 * 128 * GPAD + ((s) * 128 + (r)) * GPAD + (c))

// ---------------------------------------------------------------------------
// Epilogue. EPI: 0=bias, 1=bias+gelu, 2=bias+LN+addv, 3=bias+resid+LN
// RND: store tf32-rounded (output feeds a later GEMM as A)
// ---------------------------------------------------------------------------
template <int EPI, int RND>
__device__ __forceinline__ void epi_store(
    float acc[4][4][4],
    const float* __restrict__ bias,
    const float* __restrict__ lng, const float* __restrict__ lnb,
    const float* __restrict__ addv,
    const float* __restrict__ resid, int rstride,
    float* __restrict__ out, int ostride, int m0, int M)
{
    __shared__ float2 pbuf[128][4];
    const int tid = threadIdx.x, wid = tid >> 5, lane = tid & 31;
    const int wm = (wid & 1) * 64, wn = (wid >> 1) * 32, wq = wid >> 1;
    const int g = lane >> 2, t4 = lane & 3;

    float b2[4][2];
#pragma unroll
    for (int nt = 0; nt < 4; ++nt) {
        const int col = wn + nt * 8 + t4 * 2;
        b2[nt][0] = bias[col]; b2[nt][1] = bias[col + 1];
    }

    if (EPI <= 1) {
#pragma unroll
        for (int mt = 0; mt < 4; ++mt)
#pragma unroll
        for (int hf = 0; hf < 2; ++hf) {
            const int r = m0 + wm + mt * 16 + hf * 8 + g;
            if (r < M) {
                float* orow = out + (long)r * ostride;
#pragma unroll
                for (int nt = 0; nt < 4; ++nt) {
                    const int col = wn + nt * 8 + t4 * 2;
                    float c0 = acc[mt][nt][hf * 2 + 0] + b2[nt][0];
                    float c1 = acc[mt][nt][hf * 2 + 1] + b2[nt][1];
                    if (EPI == 1) {
                        c0 = c0 * 0.5f * (1.0f + erff(c0 * 0.70710678118654752f));
                        c1 = c1 * 0.5f * (1.0f + erff(c1 * 0.70710678118654752f));
                    }
                    if (RND) { c0 = tfr(c0); c1 = tfr(c1); }
                    *(float2*)(orow + col) = make_float2(c0, c1);
                }
            }
        }
        return;
    }

    // LN path
#pragma unroll
    for (int mt = 0; mt < 4; ++mt)
#pragma unroll
    for (int hf = 0; hf < 2; ++hf) {
        const int lr = wm + mt * 16 + hf * 8 + g;
        const int r  = m0 + lr;
        float s = 0.f, s2 = 0.f;
        const float* rrow = (EPI == 3) ? resid + (long)min(r, M - 1) * rstride : (const float*)0;
#pragma unroll
        for (int nt = 0; nt < 4; ++nt) {
            const int col = wn + nt * 8 + t4 * 2;
            float c0 = acc[mt][nt][hf * 2 + 0] + b2[nt][0];
            float c1 = acc[mt][nt][hf * 2 + 1] + b2[nt][1];
            if (EPI == 3) {
                const float2 rv = *(const float2*)(rrow + col);
                c0 += rv.x; c1 += rv.y;
            }
            acc[mt][nt][hf * 2 + 0] = c0; acc[mt][nt][hf * 2 + 1] = c1;
            s += c0 + c1; s2 += c0 * c0 + c1 * c1;
        }
        s  += __shfl_xor_sync(0xffffffffu, s, 1);
        s  += __shfl_xor_sync(0xffffffffu, s, 2);
        s2 += __shfl_xor_sync(0xffffffffu, s2, 1);
        s2 += __shfl_xor_sync(0xffffffffu, s2, 2);
        if (t4 == 0) pbuf[lr][wq] = make_float2(s, s2);
    }
    __syncthreads();
#pragma unroll
    for (int mt = 0; mt < 4; ++mt)
#pragma unroll
    for (int hf = 0; hf < 2; ++hf) {
        const int lr = wm + mt * 16 + hf * 8 + g;
        const int r  = m0 + lr;
        const float2 p0 = pbuf[lr][0], p1 = pbuf[lr][1], p2 = pbuf[lr][2], p3 = pbuf[lr][3];
        const float s    = p0.x + p1.x + p2.x + p3.x;
        const float s2   = p0.y + p1.y + p2.y + p3.y;
        const float mean = s * 0.0078125f;
        const float var  = s2 * 0.0078125f - mean * mean;
        const float rs   = rsqrtf(var + 1e-5f);
        if (r < M) {
            float* orow = out + (long)r * ostride;
#pragma unroll
            for (int nt = 0; nt < 4; ++nt) {
                const int col = wn + nt * 8 + t4 * 2;
                float o0 = (acc[mt][nt][hf * 2 + 0] - mean) * rs * lng[col]     + lnb[col];
                float o1 = (acc[mt][nt][hf * 2 + 1] - mean) * rs * lng[col + 1] + lnb[col + 1];
                if (EPI == 2) { o0 += addv[col]; o1 += addv[col + 1]; }
                if (RND) { o0 = tfr(o0); o1 = tfr(o1); }
                *(float2*)(orow + col) = make_float2(o0, o1);
            }
        }
    }
}

// ---------------------------------------------------------------------------
// Generic GEMM core (R9): 256 thr / 8 warps, warp tile 64x32, 3-stage BK=16,
// k-slot permutation (LDS.64 fragments).
// ---------------------------------------------------------------------------
template <int EPI, int RND, int CVTA>
__device__ __forceinline__ void mma_gemm(
    const float* __restrict__ A, int lda,
    const float* __restrict__ W, int K,
    const float* __restrict__ bias,
    const float* __restrict__ lng, const float* __restrict__ lnb,
    const float* __restrict__ addv,
    const float* __restrict__ resid, int rstride,
    float* __restrict__ out, int ostride,
    int m0, int M)
{
    extern __shared__ float smem[];

    __syncthreads();   // guard smem reuse across consecutive calls

    const int tid   = threadIdx.x;
    const int ldRow = tid >> 1;
    const int ldCol = (tid & 1) * 8;

    const float* Aptr = A + (long)min(m0 + ldRow, M - 1) * lda + ldCol;
    const float* Wptr = W + (long)ldRow * K + ldCol;

    unsigned sa[3], sw[3];
#pragma unroll
    for (int s = 0; s < 3; ++s) {
        sa[s] = (unsigned)__cvta_generic_to_shared(&smem[AS_IDX(s, ldRow, ldCol)]);
        sw[s] = (unsigned)__cvta_generic_to_shared(&smem[WS_IDX(s, ldRow, ldCol)]);
    }

    const int wid = tid >> 5, lane = tid & 31;
    const int wm = (wid & 1) * 64;
    const int wn = (wid >> 1) * 32;
    const int g  = lane >> 2, t4 = lane & 3;
    const int kp = 2 * t4;

    float acc[4][4][4] = {};
    const int ntiles = K >> 4;

#pragma unroll
    for (int p = 0; p < 2; ++p) {
        const int k0 = p << 4;
        cp16(sa[p],      Aptr + k0);
        cp16(sa[p] + 16, Aptr + k0 + 4);
        cp16(sw[p],      Wptr + k0);
        cp16(sw[p] + 16, Wptr + k0 + 4);
        cp_commit();
    }

    int cur = 0;
    for (int t = 0; t < ntiles; ++t) {
        if (t + 2 < ntiles) cp_wait<1>(); else cp_wait<0>();
        __syncthreads();

        if (t + 2 < ntiles) {
            const int buf = (cur + 2 >= 3) ? cur - 1 : cur + 2;
            const int k0 = (t + 2) << 4;
            cp16(sa[buf],      Aptr + k0);
            cp16(sa[buf] + 16, Aptr + k0 + 4);
            cp16(sw[buf],      Wptr + k0);
            cp16(sw[buf] + 16, Wptr + k0 + 4);
            cp_commit();
        }

#pragma unroll
        for (int ks = 0; ks < 16; ks += 8) {
            unsigned af[4][4];
#pragma unroll
            for (int mt = 0; mt < 4; ++mt) {
                const int r = wm + mt * 16 + g;
                const float2 a01 = *(const float2*)&smem[AS_IDX(cur, r,     ks + kp)];
                const float2 a23 = *(const float2*)&smem[AS_IDX(cur, r + 8, ks + kp)];
                if (CVTA) {
                    af[mt][0] = f2tf(a01.x); af[mt][2] = f2tf(a01.y);
                    af[mt][1] = f2tf(a23.x); af[mt][3] = f2tf(a23.y);
                } else {
                    af[mt][0] = __float_as_uint(a01.x); af[mt][2] = __float_as_uint(a01.y);
                    af[mt][1] = __float_as_uint(a23.x); af[mt][3] = __float_as_uint(a23.y);
                }
            }
            unsigned bf[4][2];
#pragma unroll
            for (int nt = 0; nt < 4; ++nt) {
                const int n = wn + nt * 8 + g;
                const float2 b01 = *(const float2*)&smem[WS_IDX(cur, n, ks + kp)];
                bf[nt][0] = __float_as_uint(b01.x);
                bf[nt][1] = __float_as_uint(b01.y);
            }
#pragma unroll
            for (int mt = 0; mt < 4; ++mt)
#pragma unroll
                for (int nt = 0; nt < 4; ++nt)
                    mma8(acc[mt][nt], af[mt], bf[nt]);
        }
        cur = (cur + 1 >= 3) ? 0 : cur + 1;
    }

    epi_store<EPI, RND>(acc, bias, lng, lnb, addv, resid, rstride, out, ostride, m0, M);
}

// ---------------- GEMM wrappers (generic path) ----------------

__global__ __launch_bounds__(256, 2) void k_g_spatial(
    const float* __restrict__ X,
    const float* __restrict__ pb, const float* __restrict__ lng,
    const float* __restrict__ lnb, const float* __restrict__ mod, int M)
{
    mma_gemm<2, 1, 1>(X, 1280, g_wtf + WOFF_SPATIAL, 1280, pb, lng, lnb, mod,
                      nullptr, 0, g_P, 384, blockIdx.x * 128, M);
}

__global__ __launch_bounds__(256, 2) void k_g_gf(
    const float* __restrict__ Xg, const float* __restrict__ Xf,
    const float* __restrict__ pb,
    const float* __restrict__ lng, const float* __restrict__ lnb,
    const float* __restrict__ mod, int M)
{
    const int s = blockIdx.y;     // 0->grad(n=1), 1->freq(n=2)
    const int n = s + 1;
    mma_gemm<2, 1, 1>(s ? Xf : Xg, 128, g_wtf + WOFF_GF + s * 128 * 128, 128,
                      pb + n * 128, lng + n * 128, lnb + n * 128, mod + n * 128,
                      nullptr, 0, g_P + n * 128, 384, blockIdx.x * 128, M);
}

__global__ __launch_bounds__(256, 2) void k_g_qkv(
    const float* __restrict__ Bi, int M)
{
    const int s  = blockIdx.y;
    const int m0 = blockIdx.x * 128;
    const float* A = g_P + s * 128;
    float* bufs[3] = {g_q, g_k, g_v};
#pragma unroll 1
    for (int j = 0; j < 5; ++j) {
        const int woff = qkv_jobs[s][j][0];
        const int boff = qkv_jobs[s][j][1];
        const int bid  = qkv_jobs[s][j][2];
        const int ooff = qkv_jobs[s][j][3];
        mma_gemm<0, 0, 0>(A, 384, g_wtf + WOFF_INW + woff, 128, Bi + boff,
                          nullptr, nullptr, nullptr, nullptr, 0,
                          bufs[bid] + ooff, bid == 0 ? 384 : 768, m0, M);
    }
}

__global__ __launch_bounds__(256, 2) void k_g_ffn1(
    const float* __restrict__ B1, int M)
{
    const int n  = blockIdx.y;
    const int m0 = blockIdx.x * 128;
#pragma unroll 1
    for (int tl = 0; tl < 2; ++tl)
        mma_gemm<1, 1, 0>(g_x1 + n * 128, 384,
                          g_wtf + WOFF_FFN1 + n * 256 * 128 + tl * 128 * 128, 128,
                          B1 + n * 256 + tl * 128,
                          nullptr, nullptr, nullptr, nullptr, 0,
                          g_h + n * 256 + tl * 128, 768, m0, M);
}

__global__ __launch_bounds__(256, 2) void k_g_ffn2(
    const float* __restrict__ B2,
    const float* __restrict__ fg, const float* __restrict__ fb, int M)
{
    const int n = blockIdx.y;
    mma_gemm<3, 0, 0>(g_h + n * 256, 768, g_wtf + WOFF_FFN2 + n * 128 * 256, 256,
                      B2 + n * 128, fg + n * 128, fb + n * 128, nullptr,
                      g_x1 + n * 128, 384, g_x2 + n * 128, 384, blockIdx.x * 128, M);
}

// ---------------------------------------------------------------------------
// Fused attention + outproj: per-CTA, 256 threads.
//   Phase 1 (staging): thread (r=tid>>1, h=tid&1) computes attention output
//     o[row=m0+r, cols h*64..h*64+63] thread-locally (2 heads, 2 keys) and
//     stores tf32-rounded into resident Af[128][AFPAD].
//   Phase 2: GEMM x1 = LN(o @ Wo^T + bo + P), W-only 3-stage pipeline.
// ---------------------------------------------------------------------------
__global__ __launch_bounds__(256, 2) void k_g_outproj(
    const float* __restrict__ bo,
    const float* __restrict__ ag, const float* __restrict__ ab, int M)
{
    extern __shared__ float smem[];
    const int n = blockIdx.y, m0 = blockIdx.x * 128;
    const int tid = threadIdx.x;

    // ---- W pipeline prologue (async, overlaps attention staging) ----
    const int ldRow = tid >> 1, ldCol = (tid & 1) * 8;
    const float* Wptr = g_wtf + WOFF_OUTW + n * 16384 + (long)ldRow * 128 + ldCol;
    unsigned sw[3];
#pragma unroll
    for (int s = 0; s < 3; ++s)
        sw[s] = (unsigned)__cvta_generic_to_shared(&smem[OWS_IDX(s, ldRow, ldCol)]);
#pragma unroll
    for (int p = 0; p < 2; ++p) {
        const int k0 = p << 4;
        cp16(sw[p],      Wptr + k0);
        cp16(sw[p] + 16, Wptr + k0 + 4);
        cp_commit();
    }

    // ---- attention staging into Af ----
    {
        const int r = tid >> 1, h = tid & 1;
        const int row = min(m0 + r, M - 1);
        const float* qr = g_q + (long)row * 384 + n * 128 + h * 64;
        const float* kr = g_k + (long)row * 768 + n * 256 + h * 64;
        const float* vr = g_v + (long)row * 768 + n * 256 + h * 64;
        float* af = smem + r * AFPAD + h * 64;
        const float scale = 0.17677669529663687f;   // 1/sqrt(32)
#pragma unroll
        for (int hh = 0; hh < 2; ++hh) {
            float s0 = 0.f, s1 = 0.f;
#pragma unroll
            for (int j = 0; j < 8; ++j) {
                const float4 q4  = *(const float4*)(qr + hh * 32 + j * 4);
                const float4 k04 = *(const float4*)(kr + hh * 32 + j * 4);
                const float4 k14 = *(const float4*)(kr + 128 + hh * 32 + j * 4);
                s0 += q4.x * k04.x + q4.y * k04.y + q4.z * k04.z + q4.w * k04.w;
                s1 += q4.x * k14.x + q4.y * k14.y + q4.z * k14.z + q4.w * k14.w;
            }
            s0 *= scale; s1 *= scale;
            const float mx = fmaxf(s0, s1);
            const float e0 = expf(s0 - mx), e1 = expf(s1 - mx);
            const float inv = 1.0f / (e0 + e1);
            const float w0 = e0 * inv, w1 = e1 * inv;
#pragma unroll
            for (int j = 0; j < 8; ++j) {
                const float4 v04 = *(const float4*)(vr + hh * 32 + j * 4);
                const float4 v14 = *(const float4*)(vr + 128 + hh * 32 + j * 4);
                float4 o4;
                o4.x = tfr(w0 * v04.x + w1 * v14.x);
                o4.y = tfr(w0 * v04.y + w1 * v14.y);
                o4.z = tfr(w0 * v04.z + w1 * v14.z);
                o4.w = tfr(w0 * v04.w + w1 * v14.w);
                *(float4*)(af + hh * 32 + j * 4) = o4;
            }
        }
    }

    // ---- mainloop: A resident in Af, W pipelined ----
    const int wid = tid >> 5, lane = tid & 31;
    const int wm = (wid & 1) * 64;
    const int wn = (wid >> 1) * 32;
    const int g  = lane >> 2, t4 = lane & 3;
    const int kp = 2 * t4;

    float acc[4][4][4] = {};

    int cur = 0;
    for (int t = 0; t < 8; ++t) {
        if (t + 2 < 8) cp_wait<1>(); else cp_wait<0>();
        __syncthreads();   // t=0: also makes Af stores visible

        if (t + 2 < 8) {
            const int buf = (cur + 2 >= 3) ? cur - 1 : cur + 2;
            const int k0 = (t + 2) << 4;
            cp16(sw[buf],      Wptr + k0);
            cp16(sw[buf] + 16, Wptr + k0 + 4);
            cp_commit();
        }

        const int kb = t << 4;
#pragma unroll
        for (int ks = 0; ks < 16; ks += 8) {
            unsigned af[4][4];
#pragma unroll
            for (int mt = 0; mt < 4; ++mt) {
                const int r = wm + mt * 16 + g;
                const float2 a01 = *(const float2*)&smem[r * AFPAD + kb + ks + kp];
                const float2 a23 = *(const float2*)&smem[(r + 8) * AFPAD + kb + ks + kp];
                af[mt][0] = __float_as_uint(a01.x); af[mt][2] = __float_as_uint(a01.y);
                af[mt][1] = __float_as_uint(a23.x); af[mt][3] = __float_as_uint(a23.y);
            }
            unsigned bf[4][2];
#pragma unroll
            for (int nt = 0; nt < 4; ++nt) {
                const int nn = wn + nt * 8 + g;
                const float2 b01 = *(const float2*)&smem[OWS_IDX(cur, nn, ks + kp)];
                bf[nt][0] = __float_as_uint(b01.x);
                bf[nt][1] = __float_as_uint(b01.y);
            }
#pragma unroll
            for (int mt = 0; mt < 4; ++mt)
#pragma unroll
                for (int nt = 0; nt < 4; ++nt)
                    mma8(acc[mt][nt], af[mt], bf[nt]);
        }
        cur = (cur + 1 >= 3) ? 0 : cur + 1;
    }

    epi_store<3, 1>(acc, bo + n * 128, ag + n * 128, ab + n * 128, nullptr,
                    g_P + n * 128, 384, g_x1 + n * 128, 384, m0, M);
}

// ---------------- weight tf32 pre-convert ----------------
__global__ __launch_bounds__(256) void k_cvt(
    const float* __restrict__ src, float* __restrict__ dst, int n4)
{
    const int i = blockIdx.x * 256 + threadIdx.x;
    if (i < n4) {
        const float4 v = *(const float4*)(src + 4 * i);
        float4 o;
        o.x = tfr(v.x); o.y = tfr(v.y); o.z = tfr(v.z); o.w = tfr(v.w);
        *(float4*)(dst + 4 * i) = o;
    }
}

// ---------------- gate ----------------

__global__ __launch_bounds__(256) void k_gate(
    const float* __restrict__ gw, const float* __restrict__ gb,
    float* __restrict__ out, int M)
{
    const int b = blockIdx.x * 8 + (threadIdx.x >> 5);
    if (b >= M) return;
    const int lane = threadIdx.x & 31;
    const float* xr = g_x2 + (long)b * 384;
    float l0 = 0.f, l1 = 0.f, l2 = 0.f;
#pragma unroll
    for (int j = 0; j < 12; ++j) {
        const int idx = lane + 32 * j;
        const float x = xr[idx];
        l0 += x * gw[idx];
        l1 += x * gw[384 + idx];
        l2 += x * gw[768 + idx];
    }
#pragma unroll
    for (int o = 16; o; o >>= 1) {
        l0 += __shfl_xor_sync(0xffffffffu, l0, o);
        l1 += __shfl_xor_sync(0xffffffffu, l1, o);
        l2 += __shfl_xor_sync(0xffffffffu, l2, o);
    }
    l0 += gb[0]; l1 += gb[1]; l2 += gb[2];
    const float mx = fmaxf(l0, fmaxf(l1, l2));
    const float e0 = expf(l0 - mx), e1 = expf(l1 - mx), e2 = expf(l2 - mx);
    const float inv = 1.0f / (e0 + e1 + e2);
    const float w0 = e0 * inv, w1 = e1 * inv, w2 = e2 * inv;
#pragma unroll
    for (int j = 0; j < 4; ++j) {
        const int d = lane + 32 * j;
        out[(long)b * 128 + d] = w0 * xr[d] + w1 * xr[128 + d] + w2 * xr[256 + d];
    }
}

// ---------------------------------------------------------------------------

extern "C" void kernel_launch(void* const* d_in, const int* in_sizes, int n_in,
                              void* d_out, int out_size)
{
    const float* x_spatial   = (const float*)d_in[0];
    const float* x_gradient  = (const float*)d_in[1];
    const float* x_frequency = (const float*)d_in[2];
    const float* w_spatial   = (const float*)d_in[3];
    const float* w_gf        = (const float*)d_in[4];
    const float* proj_b      = (const float*)d_in[5];
    const float* proj_ln_g   = (const float*)d_in[6];
    const float* proj_ln_b   = (const float*)d_in[7];
    const float* mod_emb     = (const float*)d_in[8];
    const float* in_w        = (const float*)d_in[9];
    const float* in_b        = (const float*)d_in[10];
    const float* out_w       = (const float*)d_in[11];
    const float* out_b       = (const float*)d_in[12];
    const float* attn_g      = (const float*)d_in[13];
    const float* attn_b      = (const float*)d_in[14];
    const float* w1          = (const float*)d_in[15];
    const float* b1          = (const float*)d_in[16];
    const float* w2          = (const float*)d_in[17];
    const float* b2          = (const float*)d_in[18];
    const float* ffn_g       = (const float*)d_in[19];
    const float* ffn_b       = (const float*)d_in[20];
    const float* gate_w      = (const float*)d_in[21];
    const float* gate_b      = (const float*)d_in[22];
    float* out = (float*)d_out;

    static int smem_set = 0;
    if (!smem_set) {
        cudaFuncSetAttribute(k_g_spatial, cudaFuncAttributeMaxDynamicSharedMemorySize, GSMEM);
        cudaFuncSetAttribute(k_g_gf,      cudaFuncAttributeMaxDynamicSharedMemorySize, GSMEM);
        cudaFuncSetAttribute(k_g_qkv,     cudaFuncAttributeMaxDynamicSharedMemorySize, GSMEM);
        cudaFuncSetAttribute(k_g_outproj, cudaFuncAttributeMaxDynamicSharedMemorySize, OSMEM);
        cudaFuncSetAttribute(k_g_ffn1,    cudaFuncAttributeMaxDynamicSharedMemorySize, GSMEM);
        cudaFuncSetAttribute(k_g_ffn2,    cudaFuncAttributeMaxDynamicSharedMemorySize, GSMEM);
        smem_set = 1;
    }

    int B = in_sizes[0] / 1280;
    if (B > MAXB) B = MAXB;
    const int gm = (B + 127) / 128;

    float* wtf;
    cudaGetSymbolAddress((void**)&wtf, g_wtf);
    k_cvt<<<(163840/4 + 255)/256, 256>>>(w_spatial, wtf + WOFF_SPATIAL, 163840/4);
    k_cvt<<<( 32768/4 + 255)/256, 256>>>(w_gf,      wtf + WOFF_GF,       32768/4);
    k_cvt<<<(147456/4 + 255)/256, 256>>>(in_w,      wtf + WOFF_INW,     147456/4);
    k_cvt<<<( 49152/4 + 255)/256, 256>>>(out_w,     wtf + WOFF_OUTW,     49152/4);
    k_cvt<<<( 98304/4 + 255)/256, 256>>>(w1,        wtf + WOFF_FFN1,     98304/4);
    k_cvt<<<( 98304/4 + 255)/256, 256>>>(w2,        wtf + WOFF_FFN2,     98304/4);

    k_g_spatial<<<gm, 256, GSMEM>>>(x_spatial, proj_b, proj_ln_g, proj_ln_b, mod_emb, B);
    k_g_gf<<<dim3(gm, 2), 256, GSMEM>>>(x_gradient, x_frequency, proj_b,
                                        proj_ln_g, proj_ln_b, mod_emb, B);
    k_g_qkv<<<dim3(gm, 3), 256, GSMEM>>>(in_b, B);
    k_g_outproj<<<dim3(gm, 3), 256, OSMEM>>>(out_b, attn_g, attn_b, B);
    k_g_ffn1<<<dim3(gm, 3), 256, GSMEM>>>(b1, B);
    k_g_ffn2<<<dim3(gm, 3), 256, GSMEM>>>(b2, ffn_g, ffn_b, B);
    k_gate<<<(B + 7) / 8, 256>>>(gate_w, gate_b, out, B);
}

// round 11
// speedup vs baseline: 1.1876x; 1.1876x over previous
#include <cuda_runtime.h>
#include <math.h>

// ---------------------------------------------------------------------------
// CMAF fused block, round 11 = round 9 +
//   (1) staged-cvt A for spatial/gf (cvt at STS, raw fragments)
//   (2) resident-A continuous-pipeline runner for qkv(5 jobs)/ffn1(2 jobs)
// k_attn restored (R10 fusion reverted).
// ---------------------------------------------------------------------------

#define MAXB 65536
#define GPAD 24
#define GSMEM (3 * 2 * 128 * GPAD * 4)   // 73728 bytes (generic path)

#define AFP 136
#define QWOFF (128 * AFP)                 // floats
#define QSMEM ((128 * AFP + 3 * 128 * GPAD) * 4)   // 106496 bytes (resident path)

__device__ __align__(16) float g_P [MAXB * 3 * 128];
__device__ __align__(16) float g_q [MAXB * 3 * 128];
__device__ __align__(16) float g_k [MAXB * 6 * 128];
__device__ __align__(16) float g_v [MAXB * 6 * 128];
__device__ __align__(16) float g_o [MAXB * 3 * 128];
__device__ __align__(16) float g_x1[MAXB * 3 * 128];
__device__ __align__(16) float g_h [MAXB * 3 * 256];
__device__ __align__(16) float g_x2[MAXB * 3 * 128];

// tf32-preconverted weights
#define WOFF_SPATIAL 0
#define WOFF_GF      163840
#define WOFF_INW     196608
#define WOFF_OUTW    344064
#define WOFF_FFN1    393216
#define WOFF_FFN2    491520
__device__ __align__(16) float g_wtf[589824];

// QKV jobs per source stream s: {w_off (within in_w), b_off, buf_id, out_off}
__constant__ int qkv_jobs[3][5][4] = {
    { {     0,    0, 0,   0}, { 65536,  512, 1, 256}, { 81920,  640, 2, 256},
      {114688,  896, 1, 512}, {131072, 1024, 2, 512} },
    { { 49152,  384, 0, 128}, { 16384,  128, 1,   0}, { 32768,  256, 2,   0},
      {114688,  896, 1, 640}, {131072, 1024, 2, 640} },
    { { 98304,  768, 0, 256}, { 16384,  128, 1, 128}, { 32768,  256, 2, 128},
      { 65536,  512, 1, 384}, { 81920,  640, 2, 384} },
};

__device__ __forceinline__ unsigned f2tf(float f) {
    unsigned u;
    asm("cvt.rna.tf32.f32 %0, %1;" : "=r"(u) : "f"(f));
    return u;
}
__device__ __forceinline__ float tfr(float f) {
    return __uint_as_float(f2tf(f));
}
__device__ __forceinline__ unsigned fau(float f) { return __float_as_uint(f); }

__device__ __forceinline__ void mma8(float c[4], const unsigned a[4], const unsigned b[2]) {
    asm volatile(
        "mma.sync.aligned.m16n8k8.row.col.f32.tf32.tf32.f32 "
        "{%0,%1,%2,%3}, {%4,%5,%6,%7}, {%8,%9}, {%0,%1,%2,%3};\n"
        : "+f"(c[0]), "+f"(c[1]), "+f"(c[2]), "+f"(c[3])
        : "r"(a[0]), "r"(a[1]), "r"(a[2]), "r"(a[3]), "r"(b[0]), "r"(b[1]));
}

__device__ __forceinline__ void cp16(unsigned smem_dst, const void* gsrc) {
    asm volatile("cp.async.cg.shared.global [%0], [%1], 16;\n"
                 :: "r"(smem_dst), "l"(gsrc));
}
__device__ __forceinline__ void cp_commit() {
    asm volatile("cp.async.commit_group;\n");
}
template <int N>
__device__ __forceinline__ void cp_wait() {
    asm volatile("cp.async.wait_group %0;\n" :: "n"(N));
}

#define AS_IDX(s, r, c) (((s) * 128 + (r)) * GPAD + (c))
#define WS_IDX(s, r, c) (3 * 128 * GPAD + ((s) * 128 + (r)) * GPAD + (c))

// ---------------------------------------------------------------------------
// Epilogue. EPI: 0=bias, 1=bias+gelu, 2=bias+LN+addv, 3=bias+resid+LN
// RND: store tf32-rounded.
// ---------------------------------------------------------------------------
template <int EPI, int RND>
__device__ __forceinline__ void epi_store(
    float acc[4][4][4],
    const float* __restrict__ bias,
    const float* __restrict__ lng, const float* __restrict__ lnb,
    const float* __restrict__ addv,
    const float* __restrict__ resid, int rstride,
    float* __restrict__ out, int ostride, int m0, int M)
{
    __shared__ float2 pbuf[128][4];
    const int tid = threadIdx.x, wid = tid >> 5, lane = tid & 31;
    const int wm = (wid & 1) * 64, wn = (wid >> 1) * 32, wq = wid >> 1;
    const int g = lane >> 2, t4 = lane & 3;

    float b2[4][2];
#pragma unroll
    for (int nt = 0; nt < 4; ++nt) {
        const int col = wn + nt * 8 + t4 * 2;
        b2[nt][0] = bias[col]; b2[nt][1] = bias[col + 1];
    }

    if (EPI <= 1) {
#pragma unroll
        for (int mt = 0; mt < 4; ++mt)
#pragma unroll
        for (int hf = 0; hf < 2; ++hf) {
            const int r = m0 + wm + mt * 16 + hf * 8 + g;
            if (r < M) {
                float* orow = out + (long)r * ostride;
#pragma unroll
                for (int nt = 0; nt < 4; ++nt) {
                    const int col = wn + nt * 8 + t4 * 2;
                    float c0 = acc[mt][nt][hf * 2 + 0] + b2[nt][0];
                    float c1 = acc[mt][nt][hf * 2 + 1] + b2[nt][1];
                    if (EPI == 1) {
                        c0 = c0 * 0.5f * (1.0f + erff(c0 * 0.70710678118654752f));
                        c1 = c1 * 0.5f * (1.0f + erff(c1 * 0.70710678118654752f));
                    }
                    if (RND) { c0 = tfr(c0); c1 = tfr(c1); }
                    *(float2*)(orow + col) = make_float2(c0, c1);
                }
            }
        }
        return;
    }

    // LN path
#pragma unroll
    for (int mt = 0; mt < 4; ++mt)
#pragma unroll
    for (int hf = 0; hf < 2; ++hf) {
        const int lr = wm + mt * 16 + hf * 8 + g;
        const int r  = m0 + lr;
        float s = 0.f, s2 = 0.f;
        const float* rrow = (EPI == 3) ? resid + (long)min(r, M - 1) * rstride : (const float*)0;
#pragma unroll
        for (int nt = 0; nt < 4; ++nt) {
            const int col = wn + nt * 8 + t4 * 2;
            float c0 = acc[mt][nt][hf * 2 + 0] + b2[nt][0];
            float c1 = acc[mt][nt][hf * 2 + 1] + b2[nt][1];
            if (EPI == 3) {
                const float2 rv = *(const float2*)(rrow + col);
                c0 += rv.x; c1 += rv.y;
            }
            acc[mt][nt][hf * 2 + 0] = c0; acc[mt][nt][hf * 2 + 1] = c1;
            s += c0 + c1; s2 += c0 * c0 + c1 * c1;
        }
        s  += __shfl_xor_sync(0xffffffffu, s, 1);
        s  += __shfl_xor_sync(0xffffffffu, s, 2);
        s2 += __shfl_xor_sync(0xffffffffu, s2, 1);
        s2 += __shfl_xor_sync(0xffffffffu, s2, 2);
        if (t4 == 0) pbuf[lr][wq] = make_float2(s, s2);
    }
    __syncthreads();
#pragma unroll
    for (int mt = 0; mt < 4; ++mt)
#pragma unroll
    for (int hf = 0; hf < 2; ++hf) {
        const int lr = wm + mt * 16 + hf * 8 + g;
        const int r  = m0 + lr;
        const float2 p0 = pbuf[lr][0], p1 = pbuf[lr][1], p2 = pbuf[lr][2], p3 = pbuf[lr][3];
        const float s    = p0.x + p1.x + p2.x + p3.x;
        const float s2   = p0.y + p1.y + p2.y + p3.y;
        const float mean = s * 0.0078125f;
        const float var  = s2 * 0.0078125f - mean * mean;
        const float rs   = rsqrtf(var + 1e-5f);
        if (r < M) {
            float* orow = out + (long)r * ostride;
#pragma unroll
            for (int nt = 0; nt < 4; ++nt) {
                const int col = wn + nt * 8 + t4 * 2;
                float o0 = (acc[mt][nt][hf * 2 + 0] - mean) * rs * lng[col]     + lnb[col];
                float o1 = (acc[mt][nt][hf * 2 + 1] - mean) * rs * lng[col + 1] + lnb[col + 1];
                if (EPI == 2) { o0 += addv[col]; o1 += addv[col + 1]; }
                if (RND) { o0 = tfr(o0); o1 = tfr(o1); }
                *(float2*)(orow + col) = make_float2(o0, o1);
            }
        }
    }
}

// ---------------------------------------------------------------------------
// Generic GEMM core. CVTST=1: A staged via LDG+cvt+STS (reg prefetch), raw
// fragments; CVTST=0: A via cp.async (already tf32).
// ---------------------------------------------------------------------------
template <int EPI, int RND, int CVTST>
__device__ __forceinline__ void mma_gemm(
    const float* __restrict__ A, int lda,
    const float* __restrict__ W, int K,
    const float* __restrict__ bias,
    const float* __restrict__ lng, const float* __restrict__ lnb,
    const float* __restrict__ addv,
    const float* __restrict__ resid, int rstride,
    float* __restrict__ out, int ostride,
    int m0, int M)
{
    extern __shared__ float smem[];

    __syncthreads();   // guard smem reuse across consecutive calls

    const int tid   = threadIdx.x;
    const int ldRow = tid >> 1;
    const int ldCol = (tid & 1) * 8;

    const float* Aptr = A + (long)min(m0 + ldRow, M - 1) * lda + ldCol;
    const float* Wptr = W + (long)ldRow * K + ldCol;

    unsigned sa[3], sw[3];
#pragma unroll
    for (int s = 0; s < 3; ++s) {
        sa[s] = (unsigned)__cvta_generic_to_shared(&smem[AS_IDX(s, ldRow, ldCol)]);
        sw[s] = (unsigned)__cvta_generic_to_shared(&smem[WS_IDX(s, ldRow, ldCol)]);
    }

    const int wid = tid >> 5, lane = tid & 31;
    const int wm = (wid & 1) * 64;
    const int wn = (wid >> 1) * 32;
    const int g  = lane >> 2, t4 = lane & 3;
    const int kp = 2 * t4;

    float acc[4][4][4] = {};
    const int ntiles = K >> 4;

    float4 ra, rb;   // CVTST prefetch regs
    if (CVTST) {
        const float4 t0a = *(const float4*)(Aptr);
        const float4 t0b = *(const float4*)(Aptr + 4);
        float* d = &smem[AS_IDX(0, ldRow, ldCol)];
        d[0] = tfr(t0a.x); d[1] = tfr(t0a.y); d[2] = tfr(t0a.z); d[3] = tfr(t0a.w);
        d[4] = tfr(t0b.x); d[5] = tfr(t0b.y); d[6] = tfr(t0b.z); d[7] = tfr(t0b.w);
        if (ntiles > 1) {
            ra = *(const float4*)(Aptr + 16);
            rb = *(const float4*)(Aptr + 20);
        }
        cp16(sw[0], Wptr); cp16(sw[0] + 16, Wptr + 4); cp_commit();
        cp16(sw[1], Wptr + 16); cp16(sw[1] + 16, Wptr + 20); cp_commit();
    } else {
#pragma unroll
        for (int p = 0; p < 2; ++p) {
            const int k0 = p << 4;
            cp16(sa[p],      Aptr + k0);
            cp16(sa[p] + 16, Aptr + k0 + 4);
            cp16(sw[p],      Wptr + k0);
            cp16(sw[p] + 16, Wptr + k0 + 4);
            cp_commit();
        }
    }

    int cur = 0;
    for (int t = 0; t < ntiles; ++t) {
        if (t + 2 < ntiles) cp_wait<1>(); else cp_wait<0>();
        __syncthreads();

        if (t + 2 < ntiles) {
            const int buf = (cur + 2 >= 3) ? cur - 1 : cur + 2;
            const int k0 = (t + 2) << 4;
            if (!CVTST) {
                cp16(sa[buf],      Aptr + k0);
                cp16(sa[buf] + 16, Aptr + k0 + 4);
            }
            cp16(sw[buf],      Wptr + k0);
            cp16(sw[buf] + 16, Wptr + k0 + 4);
            cp_commit();
        }

        if (CVTST) {
            if (t + 1 < ntiles) {
                const int nb = (cur + 1 >= 3) ? 0 : cur + 1;
                float* d = &smem[AS_IDX(nb, ldRow, ldCol)];
                d[0] = tfr(ra.x); d[1] = tfr(ra.y); d[2] = tfr(ra.z); d[3] = tfr(ra.w);
                d[4] = tfr(rb.x); d[5] = tfr(rb.y); d[6] = tfr(rb.z); d[7] = tfr(rb.w);
            }
            if (t + 2 < ntiles) {
                const int k0 = (t + 2) << 4;
                ra = *(const float4*)(Aptr + k0);
                rb = *(const float4*)(Aptr + k0 + 4);
            }
        }

#pragma unroll
        for (int ks = 0; ks < 16; ks += 8) {
            unsigned af[4][4];
#pragma unroll
            for (int mt = 0; mt < 4; ++mt) {
                const int r = wm + mt * 16 + g;
                const float2 a01 = *(const float2*)&smem[AS_IDX(cur, r,     ks + kp)];
                const float2 a23 = *(const float2*)&smem[AS_IDX(cur, r + 8, ks + kp)];
                af[mt][0] = fau(a01.x); af[mt][2] = fau(a01.y);
                af[mt][1] = fau(a23.x); af[mt][3] = fau(a23.y);
            }
            unsigned bf[4][2];
#pragma unroll
            for (int nt = 0; nt < 4; ++nt) {
                const int n = wn + nt * 8 + g;
                const float2 b01 = *(const float2*)&smem[WS_IDX(cur, n, ks + kp)];
                bf[nt][0] = fau(b01.x);
                bf[nt][1] = fau(b01.y);
            }
#pragma unroll
            for (int mt = 0; mt < 4; ++mt)
#pragma unroll
                for (int nt = 0; nt < 4; ++nt)
                    mma8(acc[mt][nt], af[mt], bf[nt]);
        }
        cur = (cur + 1 >= 3) ? 0 : cur + 1;
    }

    epi_store<EPI, RND>(acc, bias, lng, lnb, addv, resid, rstride, out, ostride, m0, M);
}

// ---------------------------------------------------------------------------
// Resident-A runner (K=128, NJ jobs sharing A). A staged once (cp.async, raw
// tf32), W 3-stage pipeline continuous across jobs.
// ---------------------------------------------------------------------------
template <int NJ, int EPI, int RND>
__device__ __forceinline__ void resA_run(
    const float* __restrict__ A, int lda, int m0, int M,
    const float* const* Wj, const float* const* bj,
    float* const* oj, const int* osj)
{
    extern __shared__ float smem[];
    const int tid = threadIdx.x;
    const int ldRow = tid >> 1, hh = tid & 1;

    // stage A (128x128 raw tf32) into Af[128][AFP]
    {
        const float* Ap = A + (long)min(m0 + ldRow, M - 1) * lda + hh * 64;
        const unsigned ab = (unsigned)__cvta_generic_to_shared(&smem[ldRow * AFP + hh * 64]);
#pragma unroll
        for (int c = 0; c < 16; ++c) cp16(ab + c * 16, Ap + c * 4);
    }
    unsigned sw[3];
#pragma unroll
    for (int s = 0; s < 3; ++s)
        sw[s] = (unsigned)__cvta_generic_to_shared(&smem[QWOFF + (s * 128 + ldRow) * GPAD + hh * 8]);
    {
        const float* wp0 = Wj[0] + (long)ldRow * 128 + hh * 8;
        cp16(sw[0], wp0); cp16(sw[0] + 16, wp0 + 4); cp_commit();   // group: A + W tile0
        cp16(sw[1], wp0 + 16); cp16(sw[1] + 16, wp0 + 20); cp_commit();
    }

    const int wid = tid >> 5, lane = tid & 31;
    const int wm = (wid & 1) * 64, wn = (wid >> 1) * 32;
    const int g = lane >> 2, t4 = lane & 3;
    const int kp = 2 * t4;

    float acc[4][4][4] = {};
    int cur = 0;

#pragma unroll 1
    for (int j = 0; j < NJ; ++j) {
#pragma unroll 1
        for (int t = 0; t < 8; ++t) {
            const int jt = j * 8 + t;
            if (jt + 2 < NJ * 8) cp_wait<1>(); else cp_wait<0>();
            __syncthreads();
            if (jt + 2 < NJ * 8) {
                const int pj = (jt + 2) >> 3, pt = (jt + 2) & 7;
                const float* wp = Wj[pj] + (long)ldRow * 128 + pt * 16 + hh * 8;
                const int buf = (cur + 2 >= 3) ? cur - 1 : cur + 2;
                cp16(sw[buf], wp); cp16(sw[buf] + 16, wp + 4);
                cp_commit();
            }
            const int kb = t << 4;
#pragma unroll
            for (int ks = 0; ks < 16; ks += 8) {
                unsigned af[4][4];
#pragma unroll
                for (int mt = 0; mt < 4; ++mt) {
                    const int r = wm + mt * 16 + g;
                    const float2 a01 = *(const float2*)&smem[r * AFP + kb + ks + kp];
                    const float2 a23 = *(const float2*)&smem[(r + 8) * AFP + kb + ks + kp];
                    af[mt][0] = fau(a01.x); af[mt][2] = fau(a01.y);
                    af[mt][1] = fau(a23.x); af[mt][3] = fau(a23.y);
                }
                unsigned bf[4][2];
#pragma unroll
                for (int nt = 0; nt < 4; ++nt) {
                    const int nn = wn + nt * 8 + g;
                    const float2 b01 = *(const float2*)&smem[QWOFF + (cur * 128 + nn) * GPAD + ks + kp];
                    bf[nt][0] = fau(b01.x);
                    bf[nt][1] = fau(b01.y);
                }
#pragma unroll
                for (int mt = 0; mt < 4; ++mt)
#pragma unroll
                    for (int nt = 0; nt < 4; ++nt)
                        mma8(acc[mt][nt], af[mt], bf[nt]);
            }
            cur = (cur + 1 >= 3) ? 0 : cur + 1;
        }
        epi_store<EPI, RND>(acc, bj[j], nullptr, nullptr, nullptr, nullptr, 0,
                            oj[j], osj[j], m0, M);
#pragma unroll
        for (int a = 0; a < 4; ++a)
#pragma unroll
            for (int b = 0; b < 4; ++b)
#pragma unroll
                for (int c = 0; c < 4; ++c) acc[a][b][c] = 0.f;
    }
}

// ---------------- kernels ----------------

__global__ __launch_bounds__(256, 2) void k_g_spatial(
    const float* __restrict__ X,
    const float* __restrict__ pb, const float* __restrict__ lng,
    const float* __restrict__ lnb, const float* __restrict__ mod, int M)
{
    mma_gemm<2, 1, 1>(X, 1280, g_wtf + WOFF_SPATIAL, 1280, pb, lng, lnb, mod,
                      nullptr, 0, g_P, 384, blockIdx.x * 128, M);
}

__global__ __launch_bounds__(256, 2) void k_g_gf(
    const float* __restrict__ Xg, const float* __restrict__ Xf,
    const float* __restrict__ pb,
    const float* __restrict__ lng, const float* __restrict__ lnb,
    const float* __restrict__ mod, int M)
{
    const int s = blockIdx.y;     // 0->grad(n=1), 1->freq(n=2)
    const int n = s + 1;
    mma_gemm<2, 1, 1>(s ? Xf : Xg, 128, g_wtf + WOFF_GF + s * 128 * 128, 128,
                      pb + n * 128, lng + n * 128, lnb + n * 128, mod + n * 128,
                      nullptr, 0, g_P + n * 128, 384, blockIdx.x * 128, M);
}

__global__ __launch_bounds__(256, 2) void k_g_qkv(
    const float* __restrict__ Bi, int M)
{
    const int s  = blockIdx.y;
    const int m0 = blockIdx.x * 128;
    float* bufs[3] = {g_q, g_k, g_v};
    const float* Wj[5]; const float* bj[5]; float* oj[5]; int osj[5];
#pragma unroll
    for (int j = 0; j < 5; ++j) {
        Wj[j]  = g_wtf + WOFF_INW + qkv_jobs[s][j][0];
        bj[j]  = Bi + qkv_jobs[s][j][1];
        const int bid = qkv_jobs[s][j][2];
        oj[j]  = bufs[bid] + qkv_jobs[s][j][3];
        osj[j] = (bid == 0) ? 384 : 768;
    }
    resA_run<5, 0, 0>(g_P + s * 128, 384, m0, M, Wj, bj, oj, osj);
}

__global__ __launch_bounds__(256, 2) void k_g_outproj(
    const float* __restrict__ bo,
    const float* __restrict__ ag, const float* __restrict__ ab, int M)
{
    const int n = blockIdx.y;
    mma_gemm<3, 1, 0>(g_o + n * 128, 384, g_wtf + WOFF_OUTW + n * 128 * 128, 128,
                      bo + n * 128, ag + n * 128, ab + n * 128, nullptr,
                      g_P + n * 128, 384, g_x1 + n * 128, 384, blockIdx.x * 128, M);
}

__global__ __launch_bounds__(256, 2) void k_g_ffn1(
    const float* __restrict__ B1, int M)
{
    const int n  = blockIdx.y;
    const int m0 = blockIdx.x * 128;
    const float* Wj[2] = { g_wtf + WOFF_FFN1 + n * 32768,
                           g_wtf + WOFF_FFN1 + n * 32768 + 16384 };
    const float* bj[2] = { B1 + n * 256, B1 + n * 256 + 128 };
    float* oj[2] = { g_h + n * 256, g_h + n * 256 + 128 };
    int osj[2] = { 768, 768 };
    resA_run<2, 1, 1>(g_x1 + n * 128, 384, m0, M, Wj, bj, oj, osj);
}

__global__ __launch_bounds__(256, 2) void k_g_ffn2(
    const float* __restrict__ B2,
    const float* __restrict__ fg, const float* __restrict__ fb, int M)
{
    const int n = blockIdx.y;
    mma_gemm<3, 0, 0>(g_h + n * 256, 768, g_wtf + WOFF_FFN2 + n * 128 * 256, 256,
                      B2 + n * 128, fg + n * 128, fb + n * 128, nullptr,
                      g_x1 + n * 128, 384, g_x2 + n * 128, 384, blockIdx.x * 128, M);
}

// ---------------- weight tf32 pre-convert ----------------
__global__ __launch_bounds__(256) void k_cvt(
    const float* __restrict__ src, float* __restrict__ dst, int n4)
{
    const int i = blockIdx.x * 256 + threadIdx.x;
    if (i < n4) {
        const float4 v = *(const float4*)(src + 4 * i);
        float4 o;
        o.x = tfr(v.x); o.y = tfr(v.y); o.z = tfr(v.z); o.w = tfr(v.w);
        *(float4*)(dst + 4 * i) = o;
    }
}

// ---------------- Attention + gate ----------------

__global__ __launch_bounds__(256) void k_attn(int M)
{
    const int rid = blockIdx.x * 8 + (threadIdx.x >> 5);
    if (rid >= M * 3) return;
    const int lane = threadIdx.x & 31;
    const int d4 = lane * 4;
    const long qb = (long)rid * 128;
    const long kb = (long)rid * 256;

    const float4 q4  = *(const float4*)(g_q + qb + d4);
    const float4 k04 = *(const float4*)(g_k + kb + d4);
    const float4 k14 = *(const float4*)(g_k + kb + 128 + d4);
    const float4 v04 = *(const float4*)(g_v + kb + d4);
    const float4 v14 = *(const float4*)(g_v + kb + 128 + d4);

    float s0 = q4.x * k04.x + q4.y * k04.y + q4.z * k04.z + q4.w * k04.w;
    float s1 = q4.x * k14.x + q4.y * k14.y + q4.z * k14.z + q4.w * k14.w;
#pragma unroll
    for (int o = 4; o; o >>= 1) {
        s0 += __shfl_xor_sync(0xffffffffu, s0, o);
        s1 += __shfl_xor_sync(0xffffffffu, s1, o);
    }
    const float scale = 0.17677669529663687f;
    s0 *= scale; s1 *= scale;
    const float mx = fmaxf(s0, s1);
    const float e0 = expf(s0 - mx), e1 = expf(s1 - mx);
    const float inv = 1.0f / (e0 + e1);
    const float w0 = e0 * inv, w1 = e1 * inv;

    float4 o4;   // tf32-rounded: feeds outproj GEMM as A
    o4.x = tfr(w0 * v04.x + w1 * v14.x);
    o4.y = tfr(w0 * v04.y + w1 * v14.y);
    o4.z = tfr(w0 * v04.z + w1 * v14.z);
    o4.w = tfr(w0 * v04.w + w1 * v14.w);
    *(float4*)(g_o + qb + d4) = o4;
}

__global__ __launch_bounds__(256) void k_gate(
    const float* __restrict__ gw, const float* __restrict__ gb,
    float* __restrict__ out, int M)
{
    const int b = blockIdx.x * 8 + (threadIdx.x >> 5);
    if (b >= M) return;
    const int lane = threadIdx.x & 31;
    const float* xr = g_x2 + (long)b * 384;
    float l0 = 0.f, l1 = 0.f, l2 = 0.f;
#pragma unroll
    for (int j = 0; j < 12; ++j) {
        const int idx = lane + 32 * j;
        const float x = xr[idx];
        l0 += x * gw[idx];
        l1 += x * gw[384 + idx];
        l2 += x * gw[768 + idx];
    }
#pragma unroll
    for (int o = 16; o; o >>= 1) {
        l0 += __shfl_xor_sync(0xffffffffu, l0, o);
        l1 += __shfl_xor_sync(0xffffffffu, l1, o);
        l2 += __shfl_xor_sync(0xffffffffu, l2, o);
    }
    l0 += gb[0]; l1 += gb[1]; l2 += gb[2];
    const float mx = fmaxf(l0, fmaxf(l1, l2));
    const float e0 = expf(l0 - mx), e1 = expf(l1 - mx), e2 = expf(l2 - mx);
    const float inv = 1.0f / (e0 + e1 + e2);
    const float w0 = e0 * inv, w1 = e1 * inv, w2 = e2 * inv;
#pragma unroll
    for (int j = 0; j < 4; ++j) {
        const int d = lane + 32 * j;
        out[(long)b * 128 + d] = w0 * xr[d] + w1 * xr[128 + d] + w2 * xr[256 + d];
    }
}

// ---------------------------------------------------------------------------

extern "C" void kernel_launch(void* const* d_in, const int* in_sizes, int n_in,
                              void* d_out, int out_size)
{
    const float* x_spatial   = (const float*)d_in[0];
    const float* x_gradient  = (const float*)d_in[1];
    const float* x_frequency = (const float*)d_in[2];
    const float* w_spatial   = (const float*)d_in[3];
    const float* w_gf        = (const float*)d_in[4];
    const float* proj_b      = (const float*)d_in[5];
    const float* proj_ln_g   = (const float*)d_in[6];
    const float* proj_ln_b   = (const float*)d_in[7];
    const float* mod_emb     = (const float*)d_in[8];
    const float* in_w        = (const float*)d_in[9];
    const float* in_b        = (const float*)d_in[10];
    const float* out_w       = (const float*)d_in[11];
    const float* out_b       = (const float*)d_in[12];
    const float* attn_g      = (const float*)d_in[13];
    const float* attn_b      = (const float*)d_in[14];
    const float* w1          = (const float*)d_in[15];
    const float* b1          = (const float*)d_in[16];
    const float* w2          = (const float*)d_in[17];
    const float* b2          = (const float*)d_in[18];
    const float* ffn_g       = (const float*)d_in[19];
    const float* ffn_b       = (const float*)d_in[20];
    const float* gate_w      = (const float*)d_in[21];
    const float* gate_b      = (const float*)d_in[22];
    float* out = (float*)d_out;

    static int smem_set = 0;
    if (!smem_set) {
        cudaFuncSetAttribute(k_g_spatial, cudaFuncAttributeMaxDynamicSharedMemorySize, GSMEM);
        cudaFuncSetAttribute(k_g_gf,      cudaFuncAttributeMaxDynamicSharedMemorySize, GSMEM);
        cudaFuncSetAttribute(k_g_qkv,     cudaFuncAttributeMaxDynamicSharedMemorySize, QSMEM);
        cudaFuncSetAttribute(k_g_outproj, cudaFuncAttributeMaxDynamicSharedMemorySize, GSMEM);
        cudaFuncSetAttribute(k_g_ffn1,    cudaFuncAttributeMaxDynamicSharedMemorySize, QSMEM);
        cudaFuncSetAttribute(k_g_ffn2,    cudaFuncAttributeMaxDynamicSharedMemorySize, GSMEM);
        smem_set = 1;
    }

    int B = in_sizes[0] / 1280;
    if (B > MAXB) B = MAXB;
    const int gm = (B + 127) / 128;
    const int R  = B * 3;

    float* wtf;
    cudaGetSymbolAddress((void**)&wtf, g_wtf);
    k_cvt<<<(163840/4 + 255)/256, 256>>>(w_spatial, wtf + WOFF_SPATIAL, 163840/4);
    k_cvt<<<( 32768/4 + 255)/256, 256>>>(w_gf,      wtf + WOFF_GF,       32768/4);
    k_cvt<<<(147456/4 + 255)/256, 256>>>(in_w,      wtf + WOFF_INW,     147456/4);
    k_cvt<<<( 49152/4 + 255)/256, 256>>>(out_w,     wtf + WOFF_OUTW,     49152/4);
    k_cvt<<<( 98304/4 + 255)/256, 256>>>(w1,        wtf + WOFF_FFN1,     98304/4);
    k_cvt<<<( 98304/4 + 255)/256, 256>>>(w2,        wtf + WOFF_FFN2,     98304/4);

    k_g_spatial<<<gm, 256, GSMEM>>>(x_spatial, proj_b, proj_ln_g, proj_ln_b, mod_emb, B);
    k_g_gf<<<dim3(gm, 2), 256, GSMEM>>>(x_gradient, x_frequency, proj_b,
                                        proj_ln_g, proj_ln_b, mod_emb, B);
    k_g_qkv<<<dim3(gm, 3), 256, QSMEM>>>(in_b, B);
    k_attn<<<(R + 7) / 8, 256>>>(B);
    k_g_outproj<<<dim3(gm, 3), 256, GSMEM>>>(out_b, attn_g, attn_b, B);
    k_g_ffn1<<<dim3(gm, 3), 256, QSMEM>>>(b1, B);
    k_g_ffn2<<<dim3(gm, 3), 256, GSMEM>>>(b2, ffn_g, ffn_b, B);
    k_gate<<<(B + 7) / 8, 256>>>(gate_w, gate_b, out, B);
}

// round 12
// speedup vs baseline: 1.2352x; 1.0401x over previous
#include <cuda_runtime.h>
#include <math.h>

// ---------------------------------------------------------------------------
// CMAF fused block, round 12 = round 11 +
//   (1) spatial+gf merged into one launch (co-scheduled waves hide gf)
//   (2) 6 weight-convert launches merged into 1 kernel
// ---------------------------------------------------------------------------

#define MAXB 65536
#define GPAD 24
#define GSMEM (3 * 2 * 128 * GPAD * 4)   // 73728 bytes (generic path)

#define AFP 136
#define QWOFF (128 * AFP)                 // floats
#define QSMEM ((128 * AFP + 3 * 128 * GPAD) * 4)   // 106496 bytes (resident path)

__device__ __align__(16) float g_P [MAXB * 3 * 128];
__device__ __align__(16) float g_q [MAXB * 3 * 128];
__device__ __align__(16) float g_k [MAXB * 6 * 128];
__device__ __align__(16) float g_v [MAXB * 6 * 128];
__device__ __align__(16) float g_o [MAXB * 3 * 128];
__device__ __align__(16) float g_x1[MAXB * 3 * 128];
__device__ __align__(16) float g_h [MAXB * 3 * 256];
__device__ __align__(16) float g_x2[MAXB * 3 * 128];

// tf32-preconverted weights (contiguous: spatial|gf|inw|outw|ffn1|ffn2)
#define WOFF_SPATIAL 0
#define WOFF_GF      163840
#define WOFF_INW     196608
#define WOFF_OUTW    344064
#define WOFF_FFN1    393216
#define WOFF_FFN2    491520
__device__ __align__(16) float g_wtf[589824];

// QKV jobs per source stream s: {w_off (within in_w), b_off, buf_id, out_off}
__constant__ int qkv_jobs[3][5][4] = {
    { {     0,    0, 0,   0}, { 65536,  512, 1, 256}, { 81920,  640, 2, 256},
      {114688,  896, 1, 512}, {131072, 1024, 2, 512} },
    { { 49152,  384, 0, 128}, { 16384,  128, 1,   0}, { 32768,  256, 2,   0},
      {114688,  896, 1, 640}, {131072, 1024, 2, 640} },
    { { 98304,  768, 0, 256}, { 16384,  128, 1, 128}, { 32768,  256, 2, 128},
      { 65536,  512, 1, 384}, { 81920,  640, 2, 384} },
};

__device__ __forceinline__ unsigned f2tf(float f) {
    unsigned u;
    asm("cvt.rna.tf32.f32 %0, %1;" : "=r"(u) : "f"(f));
    return u;
}
__device__ __forceinline__ float tfr(float f) {
    return __uint_as_float(f2tf(f));
}
__device__ __forceinline__ unsigned fau(float f) { return __float_as_uint(f); }

__device__ __forceinline__ void mma8(float c[4], const unsigned a[4], const unsigned b[2]) {
    asm volatile(
        "mma.sync.aligned.m16n8k8.row.col.f32.tf32.tf32.f32 "
        "{%0,%1,%2,%3}, {%4,%5,%6,%7}, {%8,%9}, {%0,%1,%2,%3};\n"
        : "+f"(c[0]), "+f"(c[1]), "+f"(c[2]), "+f"(c[3])
        : "r"(a[0]), "r"(a[1]), "r"(a[2]), "r"(a[3]), "r"(b[0]), "r"(b[1]));
}

__device__ __forceinline__ void cp16(unsigned smem_dst, const void* gsrc) {
    asm volatile("cp.async.cg.shared.global [%0], [%1], 16;\n"
                 :: "r"(smem_dst), "l"(gsrc));
}
__device__ __forceinline__ void cp_commit() {
    asm volatile("cp.async.commit_group;\n");
}
template <int N>
__device__ __forceinline__ void cp_wait() {
    asm volatile("cp.async.wait_group %0;\n" :: "n"(N));
}

#define AS_IDX(s, r, c) (((s) * 128 + (r)) * GPAD + (c))
#define WS_IDX(s, r, c) (3 * 128 * GPAD + ((s) * 128 + (r)) * GPAD + (c))

// ---------------------------------------------------------------------------
// Epilogue. EPI: 0=bias, 1=bias+gelu, 2=bias+LN+addv, 3=bias+resid+LN
// RND: store tf32-rounded.
// ---------------------------------------------------------------------------
template <int EPI, int RND>
__device__ __forceinline__ void epi_store(
    float acc[4][4][4],
    const float* __restrict__ bias,
    const float* __restrict__ lng, const float* __restrict__ lnb,
    const float* __restrict__ addv,
    const float* __restrict__ resid, int rstride,
    float* __restrict__ out, int ostride, int m0, int M)
{
    __shared__ float2 pbuf[128][4];
    const int tid = threadIdx.x, wid = tid >> 5, lane = tid & 31;
    const int wm = (wid & 1) * 64, wn = (wid >> 1) * 32, wq = wid >> 1;
    const int g = lane >> 2, t4 = lane & 3;

    float b2[4][2];
#pragma unroll
    for (int nt = 0; nt < 4; ++nt) {
        const int col = wn + nt * 8 + t4 * 2;
        b2[nt][0] = bias[col]; b2[nt][1] = bias[col + 1];
    }

    if (EPI <= 1) {
#pragma unroll
        for (int mt = 0; mt < 4; ++mt)
#pragma unroll
        for (int hf = 0; hf < 2; ++hf) {
            const int r = m0 + wm + mt * 16 + hf * 8 + g;
            if (r < M) {
                float* orow = out + (long)r * ostride;
#pragma unroll
                for (int nt = 0; nt < 4; ++nt) {
                    const int col = wn + nt * 8 + t4 * 2;
                    float c0 = acc[mt][nt][hf * 2 + 0] + b2[nt][0];
                    float c1 = acc[mt][nt][hf * 2 + 1] + b2[nt][1];
                    if (EPI == 1) {
                        c0 = c0 * 0.5f * (1.0f + erff(c0 * 0.70710678118654752f));
                        c1 = c1 * 0.5f * (1.0f + erff(c1 * 0.70710678118654752f));
                    }
                    if (RND) { c0 = tfr(c0); c1 = tfr(c1); }
                    *(float2*)(orow + col) = make_float2(c0, c1);
                }
            }
        }
        return;
    }

    // LN path
#pragma unroll
    for (int mt = 0; mt < 4; ++mt)
#pragma unroll
    for (int hf = 0; hf < 2; ++hf) {
        const int lr = wm + mt * 16 + hf * 8 + g;
        const int r  = m0 + lr;
        float s = 0.f, s2 = 0.f;
        const float* rrow = (EPI == 3) ? resid + (long)min(r, M - 1) * rstride : (const float*)0;
#pragma unroll
        for (int nt = 0; nt < 4; ++nt) {
            const int col = wn + nt * 8 + t4 * 2;
            float c0 = acc[mt][nt][hf * 2 + 0] + b2[nt][0];
            float c1 = acc[mt][nt][hf * 2 + 1] + b2[nt][1];
            if (EPI == 3) {
                const float2 rv = *(const float2*)(rrow + col);
                c0 += rv.x; c1 += rv.y;
            }
            acc[mt][nt][hf * 2 + 0] = c0; acc[mt][nt][hf * 2 + 1] = c1;
            s += c0 + c1; s2 += c0 * c0 + c1 * c1;
        }
        s  += __shfl_xor_sync(0xffffffffu, s, 1);
        s  += __shfl_xor_sync(0xffffffffu, s, 2);
        s2 += __shfl_xor_sync(0xffffffffu, s2, 1);
        s2 += __shfl_xor_sync(0xffffffffu, s2, 2);
        if (t4 == 0) pbuf[lr][wq] = make_float2(s, s2);
    }
    __syncthreads();
#pragma unroll
    for (int mt = 0; mt < 4; ++mt)
#pragma unroll
    for (int hf = 0; hf < 2; ++hf) {
        const int lr = wm + mt * 16 + hf * 8 + g;
        const int r  = m0 + lr;
        const float2 p0 = pbuf[lr][0], p1 = pbuf[lr][1], p2 = pbuf[lr][2], p3 = pbuf[lr][3];
        const float s    = p0.x + p1.x + p2.x + p3.x;
        const float s2   = p0.y + p1.y + p2.y + p3.y;
        const float mean = s * 0.0078125f;
        const float var  = s2 * 0.0078125f - mean * mean;
        const float rs   = rsqrtf(var + 1e-5f);
        if (r < M) {
            float* orow = out + (long)r * ostride;
#pragma unroll
            for (int nt = 0; nt < 4; ++nt) {
                const int col = wn + nt * 8 + t4 * 2;
                float o0 = (acc[mt][nt][hf * 2 + 0] - mean) * rs * lng[col]     + lnb[col];
                float o1 = (acc[mt][nt][hf * 2 + 1] - mean) * rs * lng[col + 1] + lnb[col + 1];
                if (EPI == 2) { o0 += addv[col]; o1 += addv[col + 1]; }
                if (RND) { o0 = tfr(o0); o1 = tfr(o1); }
                *(float2*)(orow + col) = make_float2(o0, o1);
            }
        }
    }
}

// ---------------------------------------------------------------------------
// Generic GEMM core. CVTST=1: A staged via LDG+cvt+STS (reg prefetch), raw
// fragments; CVTST=0: A via cp.async (already tf32).
// ---------------------------------------------------------------------------
template <int EPI, int RND, int CVTST>
__device__ __forceinline__ void mma_gemm(
    const float* __restrict__ A, int lda,
    const float* __restrict__ W, int K,
    const float* __restrict__ bias,
    const float* __restrict__ lng, const float* __restrict__ lnb,
    const float* __restrict__ addv,
    const float* __restrict__ resid, int rstride,
    float* __restrict__ out, int ostride,
    int m0, int M)
{
    extern __shared__ float smem[];

    __syncthreads();   // guard smem reuse across consecutive calls

    const int tid   = threadIdx.x;
    const int ldRow = tid >> 1;
    const int ldCol = (tid & 1) * 8;

    const float* Aptr = A + (long)min(m0 + ldRow, M - 1) * lda + ldCol;
    const float* Wptr = W + (long)ldRow * K + ldCol;

    unsigned sa[3], sw[3];
#pragma unroll
    for (int s = 0; s < 3; ++s) {
        sa[s] = (unsigned)__cvta_generic_to_shared(&smem[AS_IDX(s, ldRow, ldCol)]);
        sw[s] = (unsigned)__cvta_generic_to_shared(&smem[WS_IDX(s, ldRow, ldCol)]);
    }

    const int wid = tid >> 5, lane = tid & 31;
    const int wm = (wid & 1) * 64;
    const int wn = (wid >> 1) * 32;
    const int g  = lane >> 2, t4 = lane & 3;
    const int kp = 2 * t4;

    float acc[4][4][4] = {};
    const int ntiles = K >> 4;

    float4 ra, rb;   // CVTST prefetch regs
    if (CVTST) {
        const float4 t0a = *(const float4*)(Aptr);
        const float4 t0b = *(const float4*)(Aptr + 4);
        float* d = &smem[AS_IDX(0, ldRow, ldCol)];
        d[0] = tfr(t0a.x); d[1] = tfr(t0a.y); d[2] = tfr(t0a.z); d[3] = tfr(t0a.w);
        d[4] = tfr(t0b.x); d[5] = tfr(t0b.y); d[6] = tfr(t0b.z); d[7] = tfr(t0b.w);
        if (ntiles > 1) {
            ra = *(const float4*)(Aptr + 16);
            rb = *(const float4*)(Aptr + 20);
        }
        cp16(sw[0], Wptr); cp16(sw[0] + 16, Wptr + 4); cp_commit();
        cp16(sw[1], Wptr + 16); cp16(sw[1] + 16, Wptr + 20); cp_commit();
    } else {
#pragma unroll
        for (int p = 0; p < 2; ++p) {
            const int k0 = p << 4;
            cp16(sa[p],      Aptr + k0);
            cp16(sa[p] + 16, Aptr + k0 + 4);
            cp16(sw[p],      Wptr + k0);
            cp16(sw[p] + 16, Wptr + k0 + 4);
            cp_commit();
        }
    }

    int cur = 0;
    for (int t = 0; t < ntiles; ++t) {
        if (t + 2 < ntiles) cp_wait<1>(); else cp_wait<0>();
        __syncthreads();

        if (t + 2 < ntiles) {
            const int buf = (cur + 2 >= 3) ? cur - 1 : cur + 2;
            const int k0 = (t + 2) << 4;
            if (!CVTST) {
                cp16(sa[buf],      Aptr + k0);
                cp16(sa[buf] + 16, Aptr + k0 + 4);
            }
            cp16(sw[buf],      Wptr + k0);
            cp16(sw[buf] + 16, Wptr + k0 + 4);
            cp_commit();
        }

        if (CVTST) {
            if (t + 1 < ntiles) {
                const int nb = (cur + 1 >= 3) ? 0 : cur + 1;
                float* d = &smem[AS_IDX(nb, ldRow, ldCol)];
                d[0] = tfr(ra.x); d[1] = tfr(ra.y); d[2] = tfr(ra.z); d[3] = tfr(ra.w);
                d[4] = tfr(rb.x); d[5] = tfr(rb.y); d[6] = tfr(rb.z); d[7] = tfr(rb.w);
            }
            if (t + 2 < ntiles) {
                const int k0 = (t + 2) << 4;
                ra = *(const float4*)(Aptr + k0);
                rb = *(const float4*)(Aptr + k0 + 4);
            }
        }

#pragma unroll
        for (int ks = 0; ks < 16; ks += 8) {
            unsigned af[4][4];
#pragma unroll
            for (int mt = 0; mt < 4; ++mt) {
                const int r = wm + mt * 16 + g;
                const float2 a01 = *(const float2*)&smem[AS_IDX(cur, r,     ks + kp)];
                const float2 a23 = *(const float2*)&smem[AS_IDX(cur, r + 8, ks + kp)];
                af[mt][0] = fau(a01.x); af[mt][2] = fau(a01.y);
                af[mt][1] = fau(a23.x); af[mt][3] = fau(a23.y);
            }
            unsigned bf[4][2];
#pragma unroll
            for (int nt = 0; nt < 4; ++nt) {
                const int n = wn + nt * 8 + g;
                const float2 b01 = *(const float2*)&smem[WS_IDX(cur, n, ks + kp)];
                bf[nt][0] = fau(b01.x);
                bf[nt][1] = fau(b01.y);
            }
#pragma unroll
            for (int mt = 0; mt < 4; ++mt)
#pragma unroll
                for (int nt = 0; nt < 4; ++nt)
                    mma8(acc[mt][nt], af[mt], bf[nt]);
        }
        cur = (cur + 1 >= 3) ? 0 : cur + 1;
    }

    epi_store<EPI, RND>(acc, bias, lng, lnb, addv, resid, rstride, out, ostride, m0, M);
}

// ---------------------------------------------------------------------------
// Resident-A runner (K=128, NJ jobs sharing A). A staged once (cp.async, raw
// tf32), W 3-stage pipeline continuous across jobs.
// ---------------------------------------------------------------------------
template <int NJ, int EPI, int RND>
__device__ __forceinline__ void resA_run(
    const float* __restrict__ A, int lda, int m0, int M,
    const float* const* Wj, const float* const* bj,
    float* const* oj, const int* osj)
{
    extern __shared__ float smem[];
    const int tid = threadIdx.x;
    const int ldRow = tid >> 1, hh = tid & 1;

    // stage A (128x128 raw tf32) into Af[128][AFP]
    {
        const float* Ap = A + (long)min(m0 + ldRow, M - 1) * lda + hh * 64;
        const unsigned ab = (unsigned)__cvta_generic_to_shared(&smem[ldRow * AFP + hh * 64]);
#pragma unroll
        for (int c = 0; c < 16; ++c) cp16(ab + c * 16, Ap + c * 4);
    }
    unsigned sw[3];
#pragma unroll
    for (int s = 0; s < 3; ++s)
        sw[s] = (unsigned)__cvta_generic_to_shared(&smem[QWOFF + (s * 128 + ldRow) * GPAD + hh * 8]);
    {
        const float* wp0 = Wj[0] + (long)ldRow * 128 + hh * 8;
        cp16(sw[0], wp0); cp16(sw[0] + 16, wp0 + 4); cp_commit();   // group: A + W tile0
        cp16(sw[1], wp0 + 16); cp16(sw[1] + 16, wp0 + 20); cp_commit();
    }

    const int wid = tid >> 5, lane = tid & 31;
    const int wm = (wid & 1) * 64, wn = (wid >> 1) * 32;
    const int g = lane >> 2, t4 = lane & 3;
    const int kp = 2 * t4;

    float acc[4][4][4] = {};
    int cur = 0;

#pragma unroll 1
    for (int j = 0; j < NJ; ++j) {
#pragma unroll 1
        for (int t = 0; t < 8; ++t) {
            const int jt = j * 8 + t;
            if (jt + 2 < NJ * 8) cp_wait<1>(); else cp_wait<0>();
            __syncthreads();
            if (jt + 2 < NJ * 8) {
                const int pj = (jt + 2) >> 3, pt = (jt + 2) & 7;
                const float* wp = Wj[pj] + (long)ldRow * 128 + pt * 16 + hh * 8;
                const int buf = (cur + 2 >= 3) ? cur - 1 : cur + 2;
                cp16(sw[buf], wp); cp16(sw[buf] + 16, wp + 4);
                cp_commit();
            }
            const int kb = t << 4;
#pragma unroll
            for (int ks = 0; ks < 16; ks += 8) {
                unsigned af[4][4];
#pragma unroll
                for (int mt = 0; mt < 4; ++mt) {
                    const int r = wm + mt * 16 + g;
                    const float2 a01 = *(const float2*)&smem[r * AFP + kb + ks + kp];
                    const float2 a23 = *(const float2*)&smem[(r + 8) * AFP + kb + ks + kp];
                    af[mt][0] = fau(a01.x); af[mt][2] = fau(a01.y);
                    af[mt][1] = fau(a23.x); af[mt][3] = fau(a23.y);
                }
                unsigned bf[4][2];
#pragma unroll
                for (int nt = 0; nt < 4; ++nt) {
                    const int nn = wn + nt * 8 + g;
                    const float2 b01 = *(const float2*)&smem[QWOFF + (cur * 128 + nn) * GPAD + ks + kp];
                    bf[nt][0] = fau(b01.x);
                    bf[nt][1] = fau(b01.y);
                }
#pragma unroll
                for (int mt = 0; mt < 4; ++mt)
#pragma unroll
                    for (int nt = 0; nt < 4; ++nt)
                        mma8(acc[mt][nt], af[mt], bf[nt]);
            }
            cur = (cur + 1 >= 3) ? 0 : cur + 1;
        }
        epi_store<EPI, RND>(acc, bj[j], nullptr, nullptr, nullptr, nullptr, 0,
                            oj[j], osj[j], m0, M);
#pragma unroll
        for (int a = 0; a < 4; ++a)
#pragma unroll
            for (int b = 0; b < 4; ++b)
#pragma unroll
                for (int c = 0; c < 4; ++c) acc[a][b][c] = 0.f;
    }
}

// ---------------- kernels ----------------

// merged spatial + gf: y=0 -> spatial (K=1280), y=1,2 -> gf stream y-1
__global__ __launch_bounds__(256, 2) void k_g_proj(
    const float* __restrict__ Xs, const float* __restrict__ Xg,
    const float* __restrict__ Xf,
    const float* __restrict__ pb, const float* __restrict__ lng,
    const float* __restrict__ lnb, const float* __restrict__ mod, int M)
{
    const int y = blockIdx.y;
    if (y == 0) {
        mma_gemm<2, 1, 1>(Xs, 1280, g_wtf + WOFF_SPATIAL, 1280, pb, lng, lnb, mod,
                          nullptr, 0, g_P, 384, blockIdx.x * 128, M);
    } else {
        const int s = y - 1, n = y;
        mma_gemm<2, 1, 1>(s ? Xf : Xg, 128, g_wtf + WOFF_GF + s * 128 * 128, 128,
                          pb + n * 128, lng + n * 128, lnb + n * 128, mod + n * 128,
                          nullptr, 0, g_P + n * 128, 384, blockIdx.x * 128, M);
    }
}

__global__ __launch_bounds__(256, 2) void k_g_qkv(
    const float* __restrict__ Bi, int M)
{
    const int s  = blockIdx.y;
    const int m0 = blockIdx.x * 128;
    float* bufs[3] = {g_q, g_k, g_v};
    const float* Wj[5]; const float* bj[5]; float* oj[5]; int osj[5];
#pragma unroll
    for (int j = 0; j < 5; ++j) {
        Wj[j]  = g_wtf + WOFF_INW + qkv_jobs[s][j][0];
        bj[j]  = Bi + qkv_jobs[s][j][1];
        const int bid = qkv_jobs[s][j][2];
        oj[j]  = bufs[bid] + qkv_jobs[s][j][3];
        osj[j] = (bid == 0) ? 384 : 768;
    }
    resA_run<5, 0, 0>(g_P + s * 128, 384, m0, M, Wj, bj, oj, osj);
}

__global__ __launch_bounds__(256, 2) void k_g_outproj(
    const float* __restrict__ bo,
    const float* __restrict__ ag, const float* __restrict__ ab, int M)
{
    const int n = blockIdx.y;
    mma_gemm<3, 1, 0>(g_o + n * 128, 384, g_wtf + WOFF_OUTW + n * 128 * 128, 128,
                      bo + n * 128, ag + n * 128, ab + n * 128, nullptr,
                      g_P + n * 128, 384, g_x1 + n * 128, 384, blockIdx.x * 128, M);
}

__global__ __launch_bounds__(256, 2) void k_g_ffn1(
    const float* __restrict__ B1, int M)
{
    const int n  = blockIdx.y;
    const int m0 = blockIdx.x * 128;
    const float* Wj[2] = { g_wtf + WOFF_FFN1 + n * 32768,
                           g_wtf + WOFF_FFN1 + n * 32768 + 16384 };
    const float* bj[2] = { B1 + n * 256, B1 + n * 256 + 128 };
    float* oj[2] = { g_h + n * 256, g_h + n * 256 + 128 };
    int osj[2] = { 768, 768 };
    resA_run<2, 1, 1>(g_x1 + n * 128, 384, m0, M, Wj, bj, oj, osj);
}

__global__ __launch_bounds__(256, 2) void k_g_ffn2(
    const float* __restrict__ B2,
    const float* __restrict__ fg, const float* __restrict__ fb, int M)
{
    const int n = blockIdx.y;
    mma_gemm<3, 0, 0>(g_h + n * 256, 768, g_wtf + WOFF_FFN2 + n * 128 * 256, 256,
                      B2 + n * 128, fg + n * 128, fb + n * 128, nullptr,
                      g_x1 + n * 128, 384, g_x2 + n * 128, 384, blockIdx.x * 128, M);
}

// ---------------- weight tf32 pre-convert (single launch) ----------------
// dst g_wtf is contiguous; sources in order with float4 prefix boundaries.
__global__ __launch_bounds__(256) void k_cvt_all(
    const float* __restrict__ s0, const float* __restrict__ s1,
    const float* __restrict__ s2, const float* __restrict__ s3,
    const float* __restrict__ s4, const float* __restrict__ s5)
{
    const int i = blockIdx.x * 256 + threadIdx.x;
    if (i >= 147456) return;
    const float* src; int base;
    if      (i <  40960) { src = s0; base = 0;      }
    else if (i <  49152) { src = s1; base = 40960;  }
    else if (i <  86016) { src = s2; base = 49152;  }
    else if (i <  98304) { src = s3; base = 86016;  }
    else if (i < 122880) { src = s4; base = 98304;  }
    else                 { src = s5; base = 122880; }
    const float4 v = ((const float4*)src)[i - base];
    float4 o;
    o.x = tfr(v.x); o.y = tfr(v.y); o.z = tfr(v.z); o.w = tfr(v.w);
    ((float4*)g_wtf)[i] = o;
}

// ---------------- Attention + gate ----------------

__global__ __launch_bounds__(256) void k_attn(int M)
{
    const int rid = blockIdx.x * 8 + (threadIdx.x >> 5);
    if (rid >= M * 3) return;
    const int lane = threadIdx.x & 31;
    const int d4 = lane * 4;
    const long qb = (long)rid * 128;
    const long kb = (long)rid * 256;

    const float4 q4  = *(const float4*)(g_q + qb + d4);
    const float4 k04 = *(const float4*)(g_k + kb + d4);
    const float4 k14 = *(const float4*)(g_k + kb + 128 + d4);
    const float4 v04 = *(const float4*)(g_v + kb + d4);
    const float4 v14 = *(const float4*)(g_v + kb + 128 + d4);

    float s0 = q4.x * k04.x + q4.y * k04.y + q4.z * k04.z + q4.w * k04.w;
    float s1 = q4.x * k14.x + q4.y * k14.y + q4.z * k14.z + q4.w * k14.w;
#pragma unroll
    for (int o = 4; o; o >>= 1) {
        s0 += __shfl_xor_sync(0xffffffffu, s0, o);
        s1 += __shfl_xor_sync(0xffffffffu, s1, o);
    }
    const float scale = 0.17677669529663687f;
    s0 *= scale; s1 *= scale;
    const float mx = fmaxf(s0, s1);
    const float e0 = expf(s0 - mx), e1 = expf(s1 - mx);
    const float inv = 1.0f / (e0 + e1);
    const float w0 = e0 * inv, w1 = e1 * inv;

    float4 o4;   // tf32-rounded: feeds outproj GEMM as A
    o4.x = tfr(w0 * v04.x + w1 * v14.x);
    o4.y = tfr(w0 * v04.y + w1 * v14.y);
    o4.z = tfr(w0 * v04.z + w1 * v14.z);
    o4.w = tfr(w0 * v04.w + w1 * v14.w);
    *(float4*)(g_o + qb + d4) = o4;
}

__global__ __launch_bounds__(256) void k_gate(
    const float* __restrict__ gw, const float* __restrict__ gb,
    float* __restrict__ out, int M)
{
    const int b = blockIdx.x * 8 + (threadIdx.x >> 5);
    if (b >= M) return;
    const int lane = threadIdx.x & 31;
    const float* xr = g_x2 + (long)b * 384;
    float l0 = 0.f, l1 = 0.f, l2 = 0.f;
#pragma unroll
    for (int j = 0; j < 12; ++j) {
        const int idx = lane + 32 * j;
        const float x = xr[idx];
        l0 += x * gw[idx];
        l1 += x * gw[384 + idx];
        l2 += x * gw[768 + idx];
    }
#pragma unroll
    for (int o = 16; o; o >>= 1) {
        l0 += __shfl_xor_sync(0xffffffffu, l0, o);
        l1 += __shfl_xor_sync(0xffffffffu, l1, o);
        l2 += __shfl_xor_sync(0xffffffffu, l2, o);
    }
    l0 += gb[0]; l1 += gb[1]; l2 += gb[2];
    const float mx = fmaxf(l0, fmaxf(l1, l2));
    const float e0 = expf(l0 - mx), e1 = expf(l1 - mx), e2 = expf(l2 - mx);
    const float inv = 1.0f / (e0 + e1 + e2);
    const float w0 = e0 * inv, w1 = e1 * inv, w2 = e2 * inv;
#pragma unroll
    for (int j = 0; j < 4; ++j) {
        const int d = lane + 32 * j;
        out[(long)b * 128 + d] = w0 * xr[d] + w1 * xr[128 + d] + w2 * xr[256 + d];
    }
}

// ---------------------------------------------------------------------------

extern "C" void kernel_launch(void* const* d_in, const int* in_sizes, int n_in,
                              void* d_out, int out_size)
{
    const float* x_spatial   = (const float*)d_in[0];
    const float* x_gradient  = (const float*)d_in[1];
    const float* x_frequency = (const float*)d_in[2];
    const float* w_spatial   = (const float*)d_in[3];
    const float* w_gf        = (const float*)d_in[4];
    const float* proj_b      = (const float*)d_in[5];
    const float* proj_ln_g   = (const float*)d_in[6];
    const float* proj_ln_b   = (const float*)d_in[7];
    const float* mod_emb     = (const float*)d_in[8];
    const float* in_w        = (const float*)d_in[9];
    const float* in_b        = (const float*)d_in[10];
    const float* out_w       = (const float*)d_in[11];
    const float* out_b       = (const float*)d_in[12];
    const float* attn_g      = (const float*)d_in[13];
    const float* attn_b      = (const float*)d_in[14];
    const float* w1          = (const float*)d_in[15];
    const float* b1          = (const float*)d_in[16];
    const float* w2          = (const float*)d_in[17];
    const float* b2          = (const float*)d_in[18];
    const float* ffn_g       = (const float*)d_in[19];
    const float* ffn_b       = (const float*)d_in[20];
    const float* gate_w      = (const float*)d_in[21];
    const float* gate_b      = (const float*)d_in[22];
    float* out = (float*)d_out;

    static int smem_set = 0;
    if (!smem_set) {
        cudaFuncSetAttribute(k_g_proj,    cudaFuncAttributeMaxDynamicSharedMemorySize, GSMEM);
        cudaFuncSetAttribute(k_g_qkv,     cudaFuncAttributeMaxDynamicSharedMemorySize, QSMEM);
        cudaFuncSetAttribute(k_g_outproj, cudaFuncAttributeMaxDynamicSharedMemorySize, GSMEM);
        cudaFuncSetAttribute(k_g_ffn1,    cudaFuncAttributeMaxDynamicSharedMemorySize, QSMEM);
        cudaFuncSetAttribute(k_g_ffn2,    cudaFuncAttributeMaxDynamicSharedMemorySize, GSMEM);
        smem_set = 1;
    }

    int B = in_sizes[0] / 1280;
    if (B > MAXB) B = MAXB;
    const int gm = (B + 127) / 128;
    const int R  = B * 3;

    k_cvt_all<<<(147456 + 255) / 256, 256>>>(w_spatial, w_gf, in_w, out_w, w1, w2);

    k_g_proj<<<dim3(gm, 3), 256, GSMEM>>>(x_spatial, x_gradient, x_frequency,
                                          proj_b, proj_ln_g, proj_ln_b, mod_emb, B);
    k_g_qkv<<<dim3(gm, 3), 256, QSMEM>>>(in_b, B);
    k_attn<<<(R + 7) / 8, 256>>>(B);
    k_g_outproj<<<dim3(gm, 3), 256, GSMEM>>>(out_b, attn_g, attn_b, B);
    k_g_ffn1<<<dim3(gm, 3), 256, QSMEM>>>(b1, B);
    k_g_ffn2<<<dim3(gm, 3), 256, GSMEM>>>(b2, ffn_g, ffn_b, B);
    k_gate<<<(B + 7) / 8, 256>>>(gate_w, gate_b, out, B);
}

// round 13
// speedup vs baseline: 1.2576x; 1.0181x over previous
#include <cuda_runtime.h>
#include <math.h>

// ---------------------------------------------------------------------------
// CMAF fused block, round 13 = round 12 +
//   LDS.128 fragment loads (any-bijection k-relabel: thread t4 owns k {4t4..4t4+3})
//   quad-XOR-swizzled 16-word smem rows (conflict-free, zero pad)
//   4-stage cp.async pipeline (prefetch distance 3)
// ---------------------------------------------------------------------------

#define MAXB 65536
#define NST 4
#define STW 2048                         // words per stage (128 rows x 16)
#define GSMEM (2 * NST * STW * 4)        // 65536 B (generic path)

#define AFP2 144                         // resident-A row stride (=16 mod 32)
#define QW2 (128 * AFP2)                 // words
#define QSMEM ((QW2 + NST * STW) * 4)    // 106496 B (resident path)

__device__ __align__(16) float g_P [MAXB * 3 * 128];
__device__ __align__(16) float g_q [MAXB * 3 * 128];
__device__ __align__(16) float g_k [MAXB * 6 * 128];
__device__ __align__(16) float g_v [MAXB * 6 * 128];
__device__ __align__(16) float g_o [MAXB * 3 * 128];
__device__ __align__(16) float g_x1[MAXB * 3 * 128];
__device__ __align__(16) float g_h [MAXB * 3 * 256];
__device__ __align__(16) float g_x2[MAXB * 3 * 128];

// tf32-preconverted weights (contiguous: spatial|gf|inw|outw|ffn1|ffn2)
#define WOFF_SPATIAL 0
#define WOFF_GF      163840
#define WOFF_INW     196608
#define WOFF_OUTW    344064
#define WOFF_FFN1    393216
#define WOFF_FFN2    491520
__device__ __align__(16) float g_wtf[589824];

// QKV jobs per source stream s: {w_off (within in_w), b_off, buf_id, out_off}
__constant__ int qkv_jobs[3][5][4] = {
    { {     0,    0, 0,   0}, { 65536,  512, 1, 256}, { 81920,  640, 2, 256},
      {114688,  896, 1, 512}, {131072, 1024, 2, 512} },
    { { 49152,  384, 0, 128}, { 16384,  128, 1,   0}, { 32768,  256, 2,   0},
      {114688,  896, 1, 640}, {131072, 1024, 2, 640} },
    { { 98304,  768, 0, 256}, { 16384,  128, 1, 128}, { 32768,  256, 2, 128},
      { 65536,  512, 1, 384}, { 81920,  640, 2, 384} },
};

__device__ __forceinline__ unsigned f2tf(float f) {
    unsigned u;
    asm("cvt.rna.tf32.f32 %0, %1;" : "=r"(u) : "f"(f));
    return u;
}
__device__ __forceinline__ float tfr(float f) {
    return __uint_as_float(f2tf(f));
}
__device__ __forceinline__ unsigned fau(float f) { return __float_as_uint(f); }

__device__ __forceinline__ void mma8(float c[4], const unsigned a[4], const unsigned b[2]) {
    asm volatile(
        "mma.sync.aligned.m16n8k8.row.col.f32.tf32.tf32.f32 "
        "{%0,%1,%2,%3}, {%4,%5,%6,%7}, {%8,%9}, {%0,%1,%2,%3};\n"
        : "+f"(c[0]), "+f"(c[1]), "+f"(c[2]), "+f"(c[3])
        : "r"(a[0]), "r"(a[1]), "r"(a[2]), "r"(a[3]), "r"(b[0]), "r"(b[1]));
}

__device__ __forceinline__ void cp16(unsigned smem_dst, const void* gsrc) {
    asm volatile("cp.async.cg.shared.global [%0], [%1], 16;\n"
                 :: "r"(smem_dst), "l"(gsrc));
}
__device__ __forceinline__ void cp_commit() {
    asm volatile("cp.async.commit_group;\n");
}
template <int N>
__device__ __forceinline__ void cp_wait() {
    asm volatile("cp.async.wait_group %0;\n" :: "n"(N));
}

// ---------------------------------------------------------------------------
// Epilogue. EPI: 0=bias, 1=bias+gelu, 2=bias+LN+addv, 3=bias+resid+LN
// RND: store tf32-rounded.
// ---------------------------------------------------------------------------
template <int EPI, int RND>
__device__ __forceinline__ void epi_store(
    float acc[4][4][4],
    const float* __restrict__ bias,
    const float* __restrict__ lng, const float* __restrict__ lnb,
    const float* __restrict__ addv,
    const float* __restrict__ resid, int rstride,
    float* __restrict__ out, int ostride, int m0, int M)
{
    __shared__ float2 pbuf[128][4];
    const int tid = threadIdx.x, wid = tid >> 5, lane = tid & 31;
    const int wm = (wid & 1) * 64, wn = (wid >> 1) * 32, wq = wid >> 1;
    const int g = lane >> 2, t4 = lane & 3;

    float b2[4][2];
#pragma unroll
    for (int nt = 0; nt < 4; ++nt) {
        const int col = wn + nt * 8 + t4 * 2;
        b2[nt][0] = bias[col]; b2[nt][1] = bias[col + 1];
    }

    if (EPI <= 1) {
#pragma unroll
        for (int mt = 0; mt < 4; ++mt)
#pragma unroll
        for (int hf = 0; hf < 2; ++hf) {
            const int r = m0 + wm + mt * 16 + hf * 8 + g;
            if (r < M) {
                float* orow = out + (long)r * ostride;
#pragma unroll
                for (int nt = 0; nt < 4; ++nt) {
                    const int col = wn + nt * 8 + t4 * 2;
                    float c0 = acc[mt][nt][hf * 2 + 0] + b2[nt][0];
                    float c1 = acc[mt][nt][hf * 2 + 1] + b2[nt][1];
                    if (EPI == 1) {
                        c0 = c0 * 0.5f * (1.0f + erff(c0 * 0.70710678118654752f));
                        c1 = c1 * 0.5f * (1.0f + erff(c1 * 0.70710678118654752f));
                    }
                    if (RND) { c0 = tfr(c0); c1 = tfr(c1); }
                    *(float2*)(orow + col) = make_float2(c0, c1);
                }
            }
        }
        return;
    }

    // LN path
#pragma unroll
    for (int mt = 0; mt < 4; ++mt)
#pragma unroll
    for (int hf = 0; hf < 2; ++hf) {
        const int lr = wm + mt * 16 + hf * 8 + g;
        const int r  = m0 + lr;
        float s = 0.f, s2 = 0.f;
        const float* rrow = (EPI == 3) ? resid + (long)min(r, M - 1) * rstride : (const float*)0;
#pragma unroll
        for (int nt = 0; nt < 4; ++nt) {
            const int col = wn + nt * 8 + t4 * 2;
            float c0 = acc[mt][nt][hf * 2 + 0] + b2[nt][0];
            float c1 = acc[mt][nt][hf * 2 + 1] + b2[nt][1];
            if (EPI == 3) {
                const float2 rv = *(const float2*)(rrow + col);
                c0 += rv.x; c1 += rv.y;
            }
            acc[mt][nt][hf * 2 + 0] = c0; acc[mt][nt][hf * 2 + 1] = c1;
            s += c0 + c1; s2 += c0 * c0 + c1 * c1;
        }
        s  += __shfl_xor_sync(0xffffffffu, s, 1);
        s  += __shfl_xor_sync(0xffffffffu, s, 2);
        s2 += __shfl_xor_sync(0xffffffffu, s2, 1);
        s2 += __shfl_xor_sync(0xffffffffu, s2, 2);
        if (t4 == 0) pbuf[lr][wq] = make_float2(s, s2);
    }
    __syncthreads();
#pragma unroll
    for (int mt = 0; mt < 4; ++mt)
#pragma unroll
    for (int hf = 0; hf < 2; ++hf) {
        const int lr = wm + mt * 16 + hf * 8 + g;
        const int r  = m0 + lr;
        const float2 p0 = pbuf[lr][0], p1 = pbuf[lr][1], p2 = pbuf[lr][2], p3 = pbuf[lr][3];
        const float s    = p0.x + p1.x + p2.x + p3.x;
        const float s2   = p0.y + p1.y + p2.y + p3.y;
        const float mean = s * 0.0078125f;
        const float var  = s2 * 0.0078125f - mean * mean;
        const float rs   = rsqrtf(var + 1e-5f);
        if (r < M) {
            float* orow = out + (long)r * ostride;
#pragma unroll
            for (int nt = 0; nt < 4; ++nt) {
                const int col = wn + nt * 8 + t4 * 2;
                float o0 = (acc[mt][nt][hf * 2 + 0] - mean) * rs * lng[col]     + lnb[col];
                float o1 = (acc[mt][nt][hf * 2 + 1] - mean) * rs * lng[col + 1] + lnb[col + 1];
                if (EPI == 2) { o0 += addv[col]; o1 += addv[col + 1]; }
                if (RND) { o0 = tfr(o0); o1 = tfr(o1); }
                *(float2*)(orow + col) = make_float2(o0, o1);
            }
        }
    }
}

// inner compute for one 16-k tile (LDS.128 fragments)
__device__ __forceinline__ void tile_mma(
    const float* __restrict__ smem, int Ab, int Astride, int Akb,
    int Wb, int wm, int wn, int g, int tq, float acc[4][4][4])
{
    float4 bf4[4];
#pragma unroll
    for (int nt = 0; nt < 4; ++nt)
        bf4[nt] = *(const float4*)&smem[Wb + (wn + nt * 8 + g) * 16 + tq];
#pragma unroll
    for (int mt = 0; mt < 4; ++mt) {
        const int r = wm + mt * 16 + g;
        const float4 a0 = *(const float4*)&smem[Ab + r * Astride + Akb + tq];
        const float4 a1 = *(const float4*)&smem[Ab + (r + 8) * Astride + Akb + tq];
        const unsigned aa0[4] = {fau(a0.x), fau(a1.x), fau(a0.y), fau(a1.y)};
        const unsigned aa1[4] = {fau(a0.z), fau(a1.z), fau(a0.w), fau(a1.w)};
#pragma unroll
        for (int nt = 0; nt < 4; ++nt) {
            const unsigned b0[2] = {fau(bf4[nt].x), fau(bf4[nt].y)};
            mma8(acc[mt][nt], aa0, b0);
            const unsigned b1[2] = {fau(bf4[nt].z), fau(bf4[nt].w)};
            mma8(acc[mt][nt], aa1, b1);
        }
    }
}

// ---------------------------------------------------------------------------
// Generic GEMM core: 4-stage cp.async, swizzled 16-word rows, LDS.128 frags.
// CVTST=1: A staged via LDG+cvt+STS (reg prefetch); CVTST=0: A via cp.async.
// ---------------------------------------------------------------------------
template <int EPI, int RND, int CVTST>
__device__ __forceinline__ void mma_gemm(
    const float* __restrict__ A, int lda,
    const float* __restrict__ W, int K,
    const float* __restrict__ bias,
    const float* __restrict__ lng, const float* __restrict__ lnb,
    const float* __restrict__ addv,
    const float* __restrict__ resid, int rstride,
    float* __restrict__ out, int ostride,
    int m0, int M)
{
    extern __shared__ float smem[];
    __syncthreads();

    const int tid   = threadIdx.x;
    const int ldRow = tid >> 1;
    const int ldCol = (tid & 1) * 8;
    const int c0    = ldCol >> 2;
    const int rsw   = ldRow & 3;

    const float* Aptr = A + (long)min(m0 + ldRow, M - 1) * lda + ldCol;
    const float* Wptr = W + (long)ldRow * K + ldCol;

    const unsigned sb  = (unsigned)__cvta_generic_to_shared(smem);
    const unsigned aq0 = sb + (ldRow * 16 + ((c0    ) ^ rsw) * 4) * 4;
    const unsigned aq1 = sb + (ldRow * 16 + ((c0 + 1) ^ rsw) * 4) * 4;
    const unsigned wq0 = aq0 + NST * STW * 4;
    const unsigned wq1 = aq1 + NST * STW * 4;
    const int d0off = ldRow * 16 + ((c0    ) ^ rsw) * 4;
    const int d1off = ldRow * 16 + ((c0 + 1) ^ rsw) * 4;

    const int wid = tid >> 5, lane = tid & 31;
    const int wm = (wid & 1) * 64, wn = (wid >> 1) * 32;
    const int g = lane >> 2, t4 = lane & 3;
    const int tq = (t4 ^ (g & 3)) * 4;

    float acc[4][4][4] = {};
    const int ntiles = K >> 4;

    float4 ra, rb;
    if (CVTST) {
        const float4 t0a = *(const float4*)(Aptr);
        const float4 t0b = *(const float4*)(Aptr + 4);
        *(float4*)&smem[d0off] = make_float4(tfr(t0a.x), tfr(t0a.y), tfr(t0a.z), tfr(t0a.w));
        *(float4*)&smem[d1off] = make_float4(tfr(t0b.x), tfr(t0b.y), tfr(t0b.z), tfr(t0b.w));
        ra = *(const float4*)(Aptr + 16);
        rb = *(const float4*)(Aptr + 20);
#pragma unroll
        for (int p = 0; p < 3; ++p) {
            cp16(wq0 + p * 8192, Wptr + p * 16);
            cp16(wq1 + p * 8192, Wptr + p * 16 + 4);
            cp_commit();
        }
    } else {
#pragma unroll
        for (int p = 0; p < 3; ++p) {
            const int k0 = p << 4;
            cp16(aq0 + p * 8192, Aptr + k0);
            cp16(aq1 + p * 8192, Aptr + k0 + 4);
            cp16(wq0 + p * 8192, Wptr + k0);
            cp16(wq1 + p * 8192, Wptr + k0 + 4);
            cp_commit();
        }
    }

    int cur = 0;
    for (int t = 0; t < ntiles; ++t) {
        if (t + 3 <= ntiles)      cp_wait<2>();
        else if (t + 2 <= ntiles) cp_wait<1>();
        else                      cp_wait<0>();
        __syncthreads();

        if (t + 3 < ntiles) {
            const int buf = (cur + 3) & 3;
            const int k0 = (t + 3) << 4;
            if (!CVTST) {
                cp16(aq0 + buf * 8192, Aptr + k0);
                cp16(aq1 + buf * 8192, Aptr + k0 + 4);
            }
            cp16(wq0 + buf * 8192, Wptr + k0);
            cp16(wq1 + buf * 8192, Wptr + k0 + 4);
            cp_commit();
        }

        if (CVTST) {
            if (t + 1 < ntiles) {
                const int nb = (cur + 1) & 3;
                *(float4*)&smem[nb * STW + d0off] =
                    make_float4(tfr(ra.x), tfr(ra.y), tfr(ra.z), tfr(ra.w));
                *(float4*)&smem[nb * STW + d1off] =
                    make_float4(tfr(rb.x), tfr(rb.y), tfr(rb.z), tfr(rb.w));
            }
            if (t + 2 < ntiles) {
                const int k0 = (t + 2) << 4;
                ra = *(const float4*)(Aptr + k0);
                rb = *(const float4*)(Aptr + k0 + 4);
            }
        }

        tile_mma(smem, cur * STW, 16, 0, NST * STW + cur * STW, wm, wn, g, tq, acc);
        cur = (cur + 1) & 3;
    }

    epi_store<EPI, RND>(acc, bias, lng, lnb, addv, resid, rstride, out, ostride, m0, M);
}

// ---------------------------------------------------------------------------
// Resident-A runner (K=128, NJ jobs sharing A). A staged once (cp.async, raw
// tf32, swizzled), W 4-stage pipeline continuous across jobs.
// ---------------------------------------------------------------------------
template <int NJ, int EPI, int RND>
__device__ __forceinline__ void resA_run(
    const float* __restrict__ A, int lda, int m0, int M,
    const float* const* Wj, const float* const* bj,
    float* const* oj, const int* osj)
{
    extern __shared__ float smem[];
    const int tid = threadIdx.x;
    const int ldRow = tid >> 1, hh = tid & 1;
    const int rsw = ldRow & 3;
    const unsigned sb = (unsigned)__cvta_generic_to_shared(smem);

    // stage A (128x128 raw tf32) into swizzled Af[128][AFP2]
    {
        const float* Ap = A + (long)min(m0 + ldRow, M - 1) * lda + hh * 64;
#pragma unroll
        for (int j = 0; j < 16; ++j) {
            const int b  = hh * 4 + (j >> 2);
            const int qn = (j & 3) ^ rsw;
            cp16(sb + (ldRow * AFP2 + b * 16 + qn * 4) * 4, Ap + 4 * j);
        }
    }
    const int c0 = hh * 2;
    const unsigned wq0 = sb + (QW2 + ldRow * 16 + ((c0    ) ^ rsw) * 4) * 4;
    const unsigned wq1 = sb + (QW2 + ldRow * 16 + ((c0 + 1) ^ rsw) * 4) * 4;
    {
        const float* wp = Wj[0] + (long)ldRow * 128 + hh * 8;
        cp16(wq0, wp); cp16(wq1, wp + 4); cp_commit();      // group 0: A + W tile0
        cp16(wq0 + 8192, wp + 16); cp16(wq1 + 8192, wp + 20); cp_commit();
        cp16(wq0 + 16384, wp + 32); cp16(wq1 + 16384, wp + 36); cp_commit();
    }

    const int wid = tid >> 5, lane = tid & 31;
    const int wm = (wid & 1) * 64, wn = (wid >> 1) * 32;
    const int g = lane >> 2, t4 = lane & 3;
    const int tq = (t4 ^ (g & 3)) * 4;
    const int NT = NJ * 8;

    float acc[4][4][4] = {};
    int cur = 0;

#pragma unroll 1
    for (int j = 0; j < NJ; ++j) {
#pragma unroll 1
        for (int t = 0; t < 8; ++t) {
            const int jt = j * 8 + t;
            if (jt + 3 <= NT)      cp_wait<2>();
            else if (jt + 2 <= NT) cp_wait<1>();
            else                   cp_wait<0>();
            __syncthreads();
            if (jt + 3 < NT) {
                const int pj = (jt + 3) >> 3, pt = (jt + 3) & 7;
                const float* wp = Wj[pj] + (long)ldRow * 128 + pt * 16 + hh * 8;
                const int buf = (cur + 3) & 3;
                cp16(wq0 + buf * 8192, wp);
                cp16(wq1 + buf * 8192, wp + 4);
                cp_commit();
            }
            tile_mma(smem, 0, AFP2, t * 16, QW2 + cur * STW, wm, wn, g, tq, acc);
            cur = (cur + 1) & 3;
        }
        epi_store<EPI, RND>(acc, bj[j], nullptr, nullptr, nullptr, nullptr, 0,
                            oj[j], osj[j], m0, M);
#pragma unroll
        for (int a = 0; a < 4; ++a)
#pragma unroll
            for (int b = 0; b < 4; ++b)
#pragma unroll
                for (int c = 0; c < 4; ++c) acc[a][b][c] = 0.f;
    }
}

// ---------------- kernels ----------------

// merged spatial + gf: y=0 -> spatial (K=1280), y=1,2 -> gf stream y-1
__global__ __launch_bounds__(256, 2) void k_g_proj(
    const float* __restrict__ Xs, const float* __restrict__ Xg,
    const float* __restrict__ Xf,
    const float* __restrict__ pb, const float* __restrict__ lng,
    const float* __restrict__ lnb, const float* __restrict__ mod, int M)
{
    const int y = blockIdx.y;
    if (y == 0) {
        mma_gemm<2, 1, 1>(Xs, 1280, g_wtf + WOFF_SPATIAL, 1280, pb, lng, lnb, mod,
                          nullptr, 0, g_P, 384, blockIdx.x * 128, M);
    } else {
        const int s = y - 1, n = y;
        mma_gemm<2, 1, 1>(s ? Xf : Xg, 128, g_wtf + WOFF_GF + s * 128 * 128, 128,
                          pb + n * 128, lng + n * 128, lnb + n * 128, mod + n * 128,
                          nullptr, 0, g_P + n * 128, 384, blockIdx.x * 128, M);
    }
}

__global__ __launch_bounds__(256, 2) void k_g_qkv(
    const float* __restrict__ Bi, int M)
{
    const int s  = blockIdx.y;
    const int m0 = blockIdx.x * 128;
    float* bufs[3] = {g_q, g_k, g_v};
    const float* Wj[5]; const float* bj[5]; float* oj[5]; int osj[5];
#pragma unroll
    for (int j = 0; j < 5; ++j) {
        Wj[j]  = g_wtf + WOFF_INW + qkv_jobs[s][j][0];
        bj[j]  = Bi + qkv_jobs[s][j][1];
        const int bid = qkv_jobs[s][j][2];
        oj[j]  = bufs[bid] + qkv_jobs[s][j][3];
        osj[j] = (bid == 0) ? 384 : 768;
    }
    resA_run<5, 0, 0>(g_P + s * 128, 384, m0, M, Wj, bj, oj, osj);
}

__global__ __launch_bounds__(256, 2) void k_g_outproj(
    const float* __restrict__ bo,
    const float* __restrict__ ag, const float* __restrict__ ab, int M)
{
    const int n = blockIdx.y;
    mma_gemm<3, 1, 0>(g_o + n * 128, 384, g_wtf + WOFF_OUTW + n * 128 * 128, 128,
                      bo + n * 128, ag + n * 128, ab + n * 128, nullptr,
                      g_P + n * 128, 384, g_x1 + n * 128, 384, blockIdx.x * 128, M);
}

__global__ __launch_bounds__(256, 2) void k_g_ffn1(
    const float* __restrict__ B1, int M)
{
    const int n  = blockIdx.y;
    const int m0 = blockIdx.x * 128;
    const float* Wj[2] = { g_wtf + WOFF_FFN1 + n * 32768,
                           g_wtf + WOFF_FFN1 + n * 32768 + 16384 };
    const float* bj[2] = { B1 + n * 256, B1 + n * 256 + 128 };
    float* oj[2] = { g_h + n * 256, g_h + n * 256 + 128 };
    int osj[2] = { 768, 768 };
    resA_run<2, 1, 1>(g_x1 + n * 128, 384, m0, M, Wj, bj, oj, osj);
}

__global__ __launch_bounds__(256, 2) void k_g_ffn2(
    const float* __restrict__ B2,
    const float* __restrict__ fg, const float* __restrict__ fb, int M)
{
    const int n = blockIdx.y;
    mma_gemm<3, 0, 0>(g_h + n * 256, 768, g_wtf + WOFF_FFN2 + n * 128 * 256, 256,
                      B2 + n * 128, fg + n * 128, fb + n * 128, nullptr,
                      g_x1 + n * 128, 384, g_x2 + n * 128, 384, blockIdx.x * 128, M);
}

// ---------------- weight tf32 pre-convert (single launch) ----------------
__global__ __launch_bounds__(256) void k_cvt_all(
    const float* __restrict__ s0, const float* __restrict__ s1,
    const float* __restrict__ s2, const float* __restrict__ s3,
    const float* __restrict__ s4, const float* __restrict__ s5)
{
    const int i = blockIdx.x * 256 + threadIdx.x;
    if (i >= 147456) return;
    const float* src; int base;
    if      (i <  40960) { src = s0; base = 0;      }
    else if (i <  49152) { src = s1; base = 40960;  }
    else if (i <  86016) { src = s2; base = 49152;  }
    else if (i <  98304) { src = s3; base = 86016;  }
    else if (i < 122880) { src = s4; base = 98304;  }
    else                 { src = s5; base = 122880; }
    const float4 v = ((const float4*)src)[i - base];
    float4 o;
    o.x = tfr(v.x); o.y = tfr(v.y); o.z = tfr(v.z); o.w = tfr(v.w);
    ((float4*)g_wtf)[i] = o;
}

// ---------------- Attention + gate ----------------

__global__ __launch_bounds__(256) void k_attn(int M)
{
    const int rid = blockIdx.x * 8 + (threadIdx.x >> 5);
    if (rid >= M * 3) return;
    const int lane = threadIdx.x & 31;
    const int d4 = lane * 4;
    const long qb = (long)rid * 128;
    const long kb = (long)rid * 256;

    const float4 q4  = *(const float4*)(g_q + qb + d4);
    const float4 k04 = *(const float4*)(g_k + kb + d4);
    const float4 k14 = *(const float4*)(g_k + kb + 128 + d4);
    const float4 v04 = *(const float4*)(g_v + kb + d4);
    const float4 v14 = *(const float4*)(g_v + kb + 128 + d4);

    float s0 = q4.x * k04.x + q4.y * k04.y + q4.z * k04.z + q4.w * k04.w;
    float s1 = q4.x * k14.x + q4.y * k14.y + q4.z * k14.z + q4.w * k14.w;
#pragma unroll
    for (int o = 4; o; o >>= 1) {
        s0 += __shfl_xor_sync(0xffffffffu, s0, o);
        s1 += __shfl_xor_sync(0xffffffffu, s1, o);
    }
    const float scale = 0.17677669529663687f;
    s0 *= scale; s1 *= scale;
    const float mx = fmaxf(s0, s1);
    const float e0 = expf(s0 - mx), e1 = expf(s1 - mx);
    const float inv = 1.0f / (e0 + e1);
    const float w0 = e0 * inv, w1 = e1 * inv;

    float4 o4;   // tf32-rounded: feeds outproj GEMM as A
    o4.x = tfr(w0 * v04.x + w1 * v14.x);
    o4.y = tfr(w0 * v04.y + w1 * v14.y);
    o4.z = tfr(w0 * v04.z + w1 * v14.z);
    o4.w = tfr(w0 * v04.w + w1 * v14.w);
    *(float4*)(g_o + qb + d4) = o4;
}

__global__ __launch_bounds__(256) void k_gate(
    const float* __restrict__ gw, const float* __restrict__ gb,
    float* __restrict__ out, int M)
{
    const int b = blockIdx.x * 8 + (threadIdx.x >> 5);
    if (b >= M) return;
    const int lane = threadIdx.x & 31;
    const float* xr = g_x2 + (long)b * 384;
    float l0 = 0.f, l1 = 0.f, l2 = 0.f;
#pragma unroll
    for (int j = 0; j < 12; ++j) {
        const int idx = lane + 32 * j;
        const float x = xr[idx];
        l0 += x * gw[idx];
        l1 += x * gw[384 + idx];
        l2 += x * gw[768 + idx];
    }
#pragma unroll
    for (int o = 16; o; o >>= 1) {
        l0 += __shfl_xor_sync(0xffffffffu, l0, o);
        l1 += __shfl_xor_sync(0xffffffffu, l1, o);
        l2 += __shfl_xor_sync(0xffffffffu, l2, o);
    }
    l0 += gb[0]; l1 += gb[1]; l2 += gb[2];
    const float mx = fmaxf(l0, fmaxf(l1, l2));
    const float e0 = expf(l0 - mx), e1 = expf(l1 - mx), e2 = expf(l2 - mx);
    const float inv = 1.0f / (e0 + e1 + e2);
    const float w0 = e0 * inv, w1 = e1 * inv, w2 = e2 * inv;
#pragma unroll
    for (int j = 0; j < 4; ++j) {
        const int d = lane + 32 * j;
        out[(long)b * 128 + d] = w0 * xr[d] + w1 * xr[128 + d] + w2 * xr[256 + d];
    }
}

// ---------------------------------------------------------------------------

extern "C" void kernel_launch(void* const* d_in, const int* in_sizes, int n_in,
                              void* d_out, int out_size)
{
    const float* x_spatial   = (const float*)d_in[0];
    const float* x_gradient  = (const float*)d_in[1];
    const float* x_frequency = (const float*)d_in[2];
    const float* w_spatial   = (const float*)d_in[3];
    const float* w_gf        = (const float*)d_in[4];
    const float* proj_b      = (const float*)d_in[5];
    const float* proj_ln_g   = (const float*)d_in[6];
    const float* proj_ln_b   = (const float*)d_in[7];
    const float* mod_emb     = (const float*)d_in[8];
    const float* in_w        = (const float*)d_in[9];
    const float* in_b        = (const float*)d_in[10];
    const float* out_w       = (const float*)d_in[11];
    const float* out_b       = (const float*)d_in[12];
    const float* attn_g      = (const float*)d_in[13];
    const float* attn_b      = (const float*)d_in[14];
    const float* w1          = (const float*)d_in[15];
    const float* b1          = (const float*)d_in[16];
    const float* w2          = (const float*)d_in[17];
    const float* b2          = (const float*)d_in[18];
    const float* ffn_g       = (const float*)d_in[19];
    const float* ffn_b       = (const float*)d_in[20];
    const float* gate_w      = (const float*)d_in[21];
    const float* gate_b      = (const float*)d_in[22];
    float* out = (float*)d_out;

    static int smem_set = 0;
    if (!smem_set) {
        cudaFuncSetAttribute(k_g_proj,    cudaFuncAttributeMaxDynamicSharedMemorySize, GSMEM);
        cudaFuncSetAttribute(k_g_qkv,     cudaFuncAttributeMaxDynamicSharedMemorySize, QSMEM);
        cudaFuncSetAttribute(k_g_outproj, cudaFuncAttributeMaxDynamicSharedMemorySize, GSMEM);
        cudaFuncSetAttribute(k_g_ffn1,    cudaFuncAttributeMaxDynamicSharedMemorySize, QSMEM);
        cudaFuncSetAttribute(k_g_ffn2,    cudaFuncAttributeMaxDynamicSharedMemorySize, GSMEM);
        smem_set = 1;
    }

    int B = in_sizes[0] / 1280;
    if (B > MAXB) B = MAXB;
    const int gm = (B + 127) / 128;
    const int R  = B * 3;

    k_cvt_all<<<(147456 + 255) / 256, 256>>>(w_spatial, w_gf, in_w, out_w, w1, w2);

    k_g_proj<<<dim3(gm, 3), 256, GSMEM>>>(x_spatial, x_gradient, x_frequency,
                                          proj_b, proj_ln_g, proj_ln_b, mod_emb, B);
    k_g_qkv<<<dim3(gm, 3), 256, QSMEM>>>(in_b, B);
    k_attn<<<(R + 7) / 8, 256>>>(B);
    k_g_outproj<<<dim3(gm, 3), 256, GSMEM>>>(out_b, attn_g, attn_b, B);
    k_g_ffn1<<<dim3(gm, 3), 256, QSMEM>>>(b1, B);
    k_g_ffn2<<<dim3(gm, 3), 256, GSMEM>>>(b2, ffn_g, ffn_b, B);
    k_gate<<<(B + 7) / 8, 256>>>(gate_w, gate_b, out, B);
}